// round 1
// baseline (speedup 1.0000x reference)
#include <cuda_runtime.h>
#include <cuda_bf16.h>

#define MATN 2048
#define NN (MATN * MATN)

// ---------------------------------------------------------------------------
// Scratch buffers (no allocation allowed -> __device__ globals).
// 7 buffers of 2048^2 floats = ~117 MB.
// ---------------------------------------------------------------------------
__device__ float g_bufs[7][NN];

// ---------------------------------------------------------------------------
// f32x2 packed helpers (Blackwell packed fp32 pipe; ptxas never auto-emits)
// ---------------------------------------------------------------------------
__device__ __forceinline__ unsigned long long pack2(float x, float y) {
    unsigned long long r;
    asm("mov.b64 %0, {%1, %2};" : "=l"(r) : "r"(__float_as_uint(x)), "r"(__float_as_uint(y)));
    return r;
}
__device__ __forceinline__ void fma2(unsigned long long& d, unsigned long long a, unsigned long long b) {
    asm("fma.rn.f32x2 %0, %1, %2, %0;" : "+l"(d) : "l"(a), "l"(b));
}
__device__ __forceinline__ void unpack2(unsigned long long v, float& x, float& y) {
    unsigned int lo, hi;
    asm("mov.b64 {%0, %1}, %2;" : "=r"(lo), "=r"(hi) : "l"(v));
    x = __uint_as_float(lo);
    y = __uint_as_float(hi);
}

// ---------------------------------------------------------------------------
// SGEMM: D = A @ B (+ C if C != nullptr).  128x128 tile, BK=8, 256 threads,
// 8x8 per thread, double-buffered SMEM, f32x2 packed inner loop.
// All dims are 2048 (multiple of 128) -> no bounds checks.
// ---------------------------------------------------------------------------
#define BM 128
#define BN 128
#define BK 8

__global__ void __launch_bounds__(256)
gemm128(const float* __restrict__ A, const float* __restrict__ B,
        const float* __restrict__ C, float* __restrict__ D)
{
    __shared__ float As[2][BK][BM];
    __shared__ float Bs[2][BK][BN];

    const int tid = threadIdx.x;
    const int tx  = tid & 15;   // output col group (8 cols)
    const int ty  = tid >> 4;   // output row group (8 rows)
    const int rowBase = blockIdx.y * BM;
    const int colBase = blockIdx.x * BN;

    // A-tile loaders: 128 rows x 8 cols, one float4 per thread, conflict-free stores
    const int aRow = tid & 127;
    const int aCol = (tid >> 7) << 2;   // 0 or 4
    // B-tile loaders: 8 rows x 128 cols, one float4 per thread
    const int bRow = tid >> 5;          // 0..7
    const int bCol = (tid & 31) << 2;   // 0..124

    const float* Aptr = A + (rowBase + aRow) * MATN + aCol;
    const float* Bptr = B + bRow * MATN + colBase + bCol;

    unsigned long long acc[8][4];
#pragma unroll
    for (int i = 0; i < 8; i++)
#pragma unroll
        for (int j = 0; j < 4; j++) acc[i][j] = 0ULL;

    // preload tile 0
    {
        float4 av = *(const float4*)Aptr;
        float4 bv = *(const float4*)Bptr;
        As[0][aCol + 0][aRow] = av.x;
        As[0][aCol + 1][aRow] = av.y;
        As[0][aCol + 2][aRow] = av.z;
        As[0][aCol + 3][aRow] = av.w;
        *(float4*)&Bs[0][bRow][bCol] = bv;
    }
    __syncthreads();

    const int KT = MATN / BK;   // 256 k-tiles
#pragma unroll 1
    for (int kt = 0; kt < KT; ++kt) {
        const int buf = kt & 1;

        float4 an, bn;
        const bool more = (kt + 1 < KT);
        if (more) {
            an = *(const float4*)(Aptr + (kt + 1) * BK);
            bn = *(const float4*)(Bptr + (kt + 1) * BK * MATN);
        }

#pragma unroll
        for (int k = 0; k < BK; ++k) {
            float4 a0 = *(const float4*)&As[buf][k][ty * 8];
            float4 a1 = *(const float4*)&As[buf][k][ty * 8 + 4];
            float4 b0 = *(const float4*)&Bs[buf][k][tx * 8];
            float4 b1 = *(const float4*)&Bs[buf][k][tx * 8 + 4];

            unsigned long long bp[4];
            bp[0] = pack2(b0.x, b0.y);
            bp[1] = pack2(b0.z, b0.w);
            bp[2] = pack2(b1.x, b1.y);
            bp[3] = pack2(b1.z, b1.w);

            float am[8] = {a0.x, a0.y, a0.z, a0.w, a1.x, a1.y, a1.z, a1.w};
#pragma unroll
            for (int i = 0; i < 8; i++) {
                unsigned long long ad = pack2(am[i], am[i]);
#pragma unroll
                for (int j = 0; j < 4; j++) fma2(acc[i][j], ad, bp[j]);
            }
        }

        if (more) {
            const int nb = buf ^ 1;
            As[nb][aCol + 0][aRow] = an.x;
            As[nb][aCol + 1][aRow] = an.y;
            As[nb][aCol + 2][aRow] = an.z;
            As[nb][aCol + 3][aRow] = an.w;
            *(float4*)&Bs[nb][bRow][bCol] = bn;
        }
        __syncthreads();
    }

    // epilogue
#pragma unroll
    for (int i = 0; i < 8; i++) {
        const int row = rowBase + ty * 8 + i;
        float* dptr = D + row * MATN + colBase + tx * 8;
        float4 v0, v1;
        unpack2(acc[i][0], v0.x, v0.y);
        unpack2(acc[i][1], v0.z, v0.w);
        unpack2(acc[i][2], v1.x, v1.y);
        unpack2(acc[i][3], v1.z, v1.w);
        if (C) {
            const float* cptr = C + row * MATN + colBase + tx * 8;
            float4 c0 = *(const float4*)cptr;
            float4 c1 = *(const float4*)(cptr + 4);
            v0.x += c0.x; v0.y += c0.y; v0.z += c0.z; v0.w += c0.w;
            v1.x += c1.x; v1.y += c1.y; v1.z += c1.z; v1.w += c1.w;
        }
        *(float4*)dptr       = v0;
        *(float4*)(dptr + 4) = v1;
    }
}

// ---------------------------------------------------------------------------
// X = scale * (A - A^T) : tiled transpose in smem
// ---------------------------------------------------------------------------
__global__ void skew_kernel(const float* __restrict__ A, float* __restrict__ X, float scale)
{
    __shared__ float tile[32][33];
    const int bx = blockIdx.x * 32;  // output col block
    const int by = blockIdx.y * 32;  // output row block
    const int txx = threadIdx.x, tyy = threadIdx.y;

    // tile[t][u] = A[bx + t][by + u]
    tile[tyy][txx] = A[(bx + tyy) * MATN + by + txx];
    __syncthreads();

    const int r = by + tyy, c = bx + txx;
    X[r * MATN + c] = scale * (A[r * MATN + c] - tile[txx][tyy]);
}

// ---------------------------------------------------------------------------
// out = cI*I + k1*x1 + k2*x2 + k3*x3 (+ k4*x4 if x4)
// ---------------------------------------------------------------------------
__global__ void poly_kernel(float* __restrict__ out,
                            const float* __restrict__ x1, const float* __restrict__ x2,
                            const float* __restrict__ x3, const float* __restrict__ x4,
                            float cI, float k1, float k2, float k3, float k4)
{
    const int idx = blockIdx.x * blockDim.x + threadIdx.x;
    if (idx >= NN) return;
    float v = k1 * x1[idx] + k2 * x2[idx] + k3 * x3[idx];
    if (x4) v += k4 * x4[idx];
    if (idx % (MATN + 1) == 0) v += cI;   // diagonal
    out[idx] = v;
}

// ---------------------------------------------------------------------------
// expm(A - A^T) via scaling(s=1) + degree-12 Taylor (Paterson-Stockmeyer q=4):
//   X  = (A - A^T)/2
//   b0 = I + X + X^2/2 + X^3/6
//   b1 = c4 I + c5 X + c6 X^2 + c7 X^3
//   T1 = c8 I + c9 X + c10 X^2 + c11 X^3 + c12 X^4
//   T2 = T1 @ X4 + b1
//   V  = T2 @ X4 + b0        (~ expm(S/2))
//   out = V @ V
// ---------------------------------------------------------------------------
extern "C" void kernel_launch(void* const* d_in, const int* in_sizes, int n_in,
                              void* d_out, int out_size)
{
    const float* A = (const float*)d_in[0];
    float* out = (float*)d_out;

    float* base = nullptr;
    cudaGetSymbolAddress((void**)&base, g_bufs);
    float* X  = base + 0 * (size_t)NN;
    float* X2 = base + 1 * (size_t)NN;
    float* X3 = base + 2 * (size_t)NN;
    float* X4 = base + 3 * (size_t)NN;
    float* T1 = base + 4 * (size_t)NN;
    float* T2 = base + 5 * (size_t)NN;
    float* B1 = base + 6 * (size_t)NN;

    const float c2  = 1.0f / 2.0f;
    const float c3  = 1.0f / 6.0f;
    const float c4  = 1.0f / 24.0f;
    const float c5  = 1.0f / 120.0f;
    const float c6  = 1.0f / 720.0f;
    const float c7  = 1.0f / 5040.0f;
    const float c8  = 1.0f / 40320.0f;
    const float c9  = 1.0f / 362880.0f;
    const float c10 = 1.0f / 3628800.0f;
    const float c11 = 1.0f / 39916800.0f;
    const float c12 = 1.0f / 479001600.0f;

    const dim3 gGrid(MATN / BN, MATN / BM);   // (16,16)
    const dim3 tGrid(MATN / 32, MATN / 32);   // (64,64)
    const int  pBlocks = (NN + 255) / 256;

    // X = (A - A^T) * 0.5
    skew_kernel<<<tGrid, dim3(32, 32)>>>(A, X, 0.5f);
    // powers
    gemm128<<<gGrid, 256>>>(X,  X,  nullptr, X2);
    gemm128<<<gGrid, 256>>>(X2, X,  nullptr, X3);
    gemm128<<<gGrid, 256>>>(X2, X2, nullptr, X4);
    // T1 = c8 I + c9 X + c10 X2 + c11 X3 + c12 X4
    poly_kernel<<<pBlocks, 256>>>(T1, X, X2, X3, X4, c8, c9, c10, c11, c12);
    // B1 = c4 I + c5 X + c6 X2 + c7 X3
    poly_kernel<<<pBlocks, 256>>>(B1, X, X2, X3, nullptr, c4, c5, c6, c7, 0.0f);
    // T2 = T1 @ X4 + B1
    gemm128<<<gGrid, 256>>>(T1, X4, B1, T2);
    // B0 = I + X + c2 X2 + c3 X3   (reuse T1 buffer)
    poly_kernel<<<pBlocks, 256>>>(T1, X, X2, X3, nullptr, 1.0f, 1.0f, c2, c3, 0.0f);
    // V = T2 @ X4 + B0   (reuse B1 buffer)
    gemm128<<<gGrid, 256>>>(T2, X4, T1, B1);
    // out = V @ V
    gemm128<<<gGrid, 256>>>(B1, B1, nullptr, out);
}

// round 5
// speedup vs baseline: 3.4949x; 3.4949x over previous
#include <cuda_runtime.h>
#include <cuda_bf16.h>
#include <cstdint>

#define MATN 2048
#define NN (MATN * MATN)
#define KP   6144                 // packed K = 3 * 2048 (bf16x3 split)
#define KC   64                   // K per stage
#define NSTAGE_ITERS (KP / KC)    // 96
#define STAGES 4
#define TILE_M 128
#define TILE_N 128

#define A_STG_BYTES (TILE_M * 128)   // 16384 (128 rows x 64 bf16, SW128-swizzled)
#define B_STG_BYTES (TILE_N * 128)   // 16384

// smem map (dynamic)
#define OFF_FULL   0                                   // 4 x 8B
#define OFF_EMPTY  32                                  // 4 x 8B
#define OFF_A      1024
#define OFF_B      (OFF_A + STAGES * A_STG_BYTES)      // 66560
#define SMEM_BYTES (OFF_B + STAGES * B_STG_BYTES)      // 132096

#define PK_BYTES ((size_t)MATN * KP * 2)   // 25165824 per packed operand

// ---------------------------------------------------------------------------
// Scratch (no allocation allowed): 7 fp32 mats + 4 packed bf16 operand bufs
// ---------------------------------------------------------------------------
__device__ float g_f[7][NN];
__device__ __align__(128) unsigned char g_pk[4][PK_BYTES];

// ---------------------------------------------------------------------------
// PTX helpers (all baseline compute_103-safe: no tcgen05 / TMEM anywhere)
// ---------------------------------------------------------------------------
__device__ __forceinline__ uint32_t smem_u32(const void* p) {
    uint32_t a;
    asm("{ .reg .u64 t; cvta.to.shared.u64 t, %1; cvt.u32.u64 %0, t; }" : "=r"(a) : "l"(p));
    return a;
}

#define MBAR_INIT(addr, cnt) \
    asm volatile("mbarrier.init.shared.b64 [%0], %1;" :: "r"(addr), "r"(cnt) : "memory")
#define MBAR_INVAL(addr) \
    asm volatile("mbarrier.inval.shared.b64 [%0];" :: "r"(addr) : "memory")
#define MBAR_EXPECT_TX(addr, bytes) \
    asm volatile("mbarrier.arrive.expect_tx.shared.b64 _, [%0], %1;" :: "r"(addr), "r"(bytes) : "memory")
#define MBAR_ARRIVE(addr) \
    asm volatile("mbarrier.arrive.shared.b64 _, [%0];" :: "r"(addr) : "memory")

#define MBAR_WAIT(addr, ph) do {                                            \
    uint32_t _m = (addr), _p = (ph), _d;                                    \
    asm volatile("{\n\t.reg .pred p;\n\t"                                   \
        "mbarrier.try_wait.parity.acquire.cta.shared::cta.b64 p, [%1], %2;\n\t" \
        "selp.b32 %0, 1, 0, p;\n\t}"                                        \
        : "=r"(_d) : "r"(_m), "r"(_p) : "memory");                          \
    if (!_d) {                                                              \
        asm volatile("{\n\t.reg .pred P1;\n\t"                              \
            "WL_%=:\n\t"                                                    \
            "mbarrier.try_wait.parity.acquire.cta.shared::cta.b64 P1, [%0], %1, 0x989680;\n\t" \
            "@P1 bra.uni WD_%=;\n\t"                                        \
            "bra.uni WL_%=;\n\t"                                            \
            "WD_%=:\n\t}" :: "r"(_m), "r"(_p) : "memory");                  \
    }                                                                       \
} while (0)

__device__ __forceinline__ void bulk_g2s(uint32_t dst, const void* src, uint32_t bytes, uint32_t mbar) {
    asm volatile(
        "cp.async.bulk.shared::cluster.global.mbarrier::complete_tx::bytes [%0], [%1], %2, [%3];"
        :: "r"(dst), "l"(src), "r"(bytes), "r"(mbar) : "memory");
}

__device__ __forceinline__ void ldsm_x4(uint32_t* r, uint32_t addr) {
    asm volatile("ldmatrix.sync.aligned.m8n8.x4.shared.b16 {%0,%1,%2,%3}, [%4];"
                 : "=r"(r[0]), "=r"(r[1]), "=r"(r[2]), "=r"(r[3]) : "r"(addr));
}

__device__ __forceinline__ void mma_bf16(float* c, const uint32_t* a, const uint32_t* b) {
    asm volatile(
        "mma.sync.aligned.m16n8k16.row.col.f32.bf16.bf16.f32 "
        "{%0,%1,%2,%3}, {%4,%5,%6,%7}, {%8,%9}, {%0,%1,%2,%3};"
        : "+f"(c[0]), "+f"(c[1]), "+f"(c[2]), "+f"(c[3])
        : "r"(a[0]), "r"(a[1]), "r"(a[2]), "r"(a[3]), "r"(b[0]), "r"(b[1]));
}

// ---------------------------------------------------------------------------
// GEMM: D[M,N](fp32) = Ap(M x KP bf16) @ Bp(N x KP bf16)^T  (+ C if C != nullptr)
// Operands pre-tiled & pre-swizzled in gmem (16KB blocks of 128 rows x 64 bf16).
// 8 compute warps (each 32x64 output) + 1 producer warp; cp.async.bulk pipeline.
// ---------------------------------------------------------------------------
__global__ void __launch_bounds__(288, 1)
gemm_bf16(const unsigned char* __restrict__ Ap, const unsigned char* __restrict__ Bp,
          const float* __restrict__ C, float* __restrict__ D)
{
    extern __shared__ __align__(1024) unsigned char smem[];
    const uint32_t sb = smem_u32(smem);
    const int tid = threadIdx.x;
    const int wid = tid >> 5;
    const int lid = tid & 31;
    const int nt = blockIdx.x;   // 0..15
    const int mt = blockIdx.y;   // 0..15

    if (tid == 0) {
        for (int s = 0; s < STAGES; s++) {
            MBAR_INIT(sb + OFF_FULL  + s * 8, 1);    // producer expect_tx arrive
            MBAR_INIT(sb + OFF_EMPTY + s * 8, 8);    // 8 consumer-warp arrivals
        }
    }
    __syncthreads();

    if (wid == 8) {
        // ---- producer (lane 0 of warp 8) ----
        if (lid == 0) {
            const unsigned char* srcA = Ap + (size_t)mt * NSTAGE_ITERS * A_STG_BYTES;
            const unsigned char* srcB = Bp + (size_t)nt * NSTAGE_ITERS * B_STG_BYTES;
            int st = 0, ph = 1;
            for (int ks = 0; ks < NSTAGE_ITERS; ++ks) {
                MBAR_WAIT(sb + OFF_EMPTY + st * 8, ph);
                MBAR_EXPECT_TX(sb + OFF_FULL + st * 8, A_STG_BYTES + B_STG_BYTES);
                bulk_g2s(sb + OFF_A + st * A_STG_BYTES, srcA + (size_t)ks * A_STG_BYTES,
                         A_STG_BYTES, sb + OFF_FULL + st * 8);
                bulk_g2s(sb + OFF_B + st * B_STG_BYTES, srcB + (size_t)ks * B_STG_BYTES,
                         B_STG_BYTES, sb + OFF_FULL + st * 8);
                if (++st == STAGES) { st = 0; ph ^= 1; }
            }
        }
        return;
    }

    // ---- consumer warps 0..7: warp tile 32(m) x 64(n) ----
    const int mb = (wid >> 1) * 32;    // warp row base within CTA tile
    const int nb = (wid & 1) * 64;     // warp col base within CTA tile

    // ldmatrix lane addressing (SW128 swizzle reduces to XOR of (row&7)<<4)
    const int rA   = mb + (lid & 15);            // A row for this lane (mi adds +16)
    const int chA  = (lid >> 4);                 // A k-chunk sub-index (0/1)
    const uint32_t xorA = (rA & 7) << 4;
    const int rB   = nb + (lid & 7) + ((lid >> 4) << 3);   // B row (n), j adds +16
    const int chB  = (lid >> 3) & 1;
    const uint32_t xorB = (rB & 7) << 4;

    float acc[2][8][4];
#pragma unroll
    for (int mi = 0; mi < 2; mi++)
#pragma unroll
        for (int j = 0; j < 8; j++)
#pragma unroll
            for (int q = 0; q < 4; q++) acc[mi][j][q] = 0.0f;

    int st = 0, ph = 0;
#pragma unroll 1
    for (int ks = 0; ks < NSTAGE_ITERS; ++ks) {
        MBAR_WAIT(sb + OFF_FULL + st * 8, ph);
        const uint32_t baseA = sb + OFF_A + st * A_STG_BYTES + (uint32_t)rA * 128;
        const uint32_t baseB = sb + OFF_B + st * B_STG_BYTES + (uint32_t)rB * 128;

#pragma unroll
        for (int kk = 0; kk < 4; ++kk) {
            uint32_t a[2][4];
            const uint32_t kcA = (uint32_t)(kk * 2 + chA) * 16 ^ xorA;
            ldsm_x4(a[0], baseA + kcA);
            ldsm_x4(a[1], baseA + 2048 + kcA);     // +16 rows

            uint32_t b[4][4];
            const uint32_t kcB = (uint32_t)(kk * 2 + chB) * 16 ^ xorB;
#pragma unroll
            for (int jj = 0; jj < 4; ++jj)
                ldsm_x4(b[jj], baseB + (uint32_t)jj * 2048 + kcB);

#pragma unroll
            for (int mi = 0; mi < 2; ++mi)
#pragma unroll
                for (int j = 0; j < 8; ++j)
                    mma_bf16(acc[mi][j], a[mi], &b[j >> 1][(j & 1) * 2]);
        }

        if (lid == 0) MBAR_ARRIVE(sb + OFF_EMPTY + st * 8);
        if (++st == STAGES) { st = 0; ph ^= 1; }
    }

    // ---- epilogue: registers -> gmem (optional C add) ----
    const int g = lid >> 2, t = lid & 3;
    const int rowBase = mt * TILE_M + mb;
    const int colBase = nt * TILE_N + nb;
#pragma unroll
    for (int mi = 0; mi < 2; ++mi) {
        const int r0 = rowBase + mi * 16 + g;
#pragma unroll
        for (int j = 0; j < 8; ++j) {
            const int c = colBase + j * 8 + t * 2;
            float2 v0 = make_float2(acc[mi][j][0], acc[mi][j][1]);
            float2 v1 = make_float2(acc[mi][j][2], acc[mi][j][3]);
            if (C) {
                float2 c0 = *(const float2*)(C + (size_t)r0 * MATN + c);
                float2 c1 = *(const float2*)(C + (size_t)(r0 + 8) * MATN + c);
                v0.x += c0.x; v0.y += c0.y;
                v1.x += c1.x; v1.y += c1.y;
            }
            *(float2*)(D + (size_t)r0 * MATN + c)       = v0;
            *(float2*)(D + (size_t)(r0 + 8) * MATN + c) = v1;
        }
    }
}

// ---------------------------------------------------------------------------
// Pack kernels: fp32 matrix -> pre-tiled pre-swizzled bf16x3 operand images.
// Block(ks) = 16KB: 128 rows x 64 bf16-cols, SW128 swizzle per 16B chunk.
// left rows = matrix rows; right rows = matrix cols (transposed).
// seg order: left [Ah|Ah|Al], right [Bh;Bl;Bh] -> AhBh + AhBl + AlBh
// ---------------------------------------------------------------------------
__device__ __forceinline__ void split_bf16(float x, __nv_bfloat16& h, __nv_bfloat16& l) {
    h = __float2bfloat16(x);
    l = __float2bfloat16(x - __bfloat162float(h));
}

__global__ void pack_L(const float* __restrict__ src, unsigned char* __restrict__ dst)
{
    const int idx = blockIdx.x * blockDim.x + threadIdx.x;
    const int row = idx >> 11, col = idx & 2047;
    __nv_bfloat16 h, l;
    split_bf16(src[idx], h, l);
    const int mtb = row >> 7, rl = row & 127;
#pragma unroll
    for (int seg = 0; seg < 3; ++seg) {
        const int kcol = seg * 2048 + col;
        const int ks = kcol >> 6, cl = kcol & 63;
        uint32_t off = (uint32_t)rl * 128 + (cl >> 3) * 16;
        off ^= (off >> 3) & 0x70;
        size_t a = ((size_t)(mtb * NSTAGE_ITERS + ks) << 14) + off + (cl & 7) * 2;
        *(__nv_bfloat16*)(dst + a) = (seg == 2) ? l : h;
    }
}

__global__ void pack_R(const float* __restrict__ src, unsigned char* __restrict__ dst)
{
    __shared__ float t[32][33];
    const int k0 = blockIdx.y * 32, n0 = blockIdx.x * 32;
    t[threadIdx.y][threadIdx.x] = src[(k0 + threadIdx.y) * MATN + n0 + threadIdx.x];
    __syncthreads();
    const int n = n0 + threadIdx.y;          // output row (src column)
    const int kc = k0 + threadIdx.x;         // base k
    __nv_bfloat16 h, l;
    split_bf16(t[threadIdx.x][threadIdx.y], h, l);
    const int ntb = n >> 7, rl = n & 127;
#pragma unroll
    for (int seg = 0; seg < 3; ++seg) {
        const int kcol = seg * 2048 + kc;
        const int ks = kcol >> 6, cl = kcol & 63;
        uint32_t off = (uint32_t)rl * 128 + (cl >> 3) * 16;
        off ^= (off >> 3) & 0x70;
        size_t a = ((size_t)(ntb * NSTAGE_ITERS + ks) << 14) + off + (cl & 7) * 2;
        *(__nv_bfloat16*)(dst + a) = (seg == 1) ? l : h;
    }
}

// ---------------------------------------------------------------------------
// X = scale * (A - A^T)
// ---------------------------------------------------------------------------
__global__ void skew_kernel(const float* __restrict__ A, float* __restrict__ X, float scale)
{
    __shared__ float tile[32][33];
    const int bx = blockIdx.x * 32, by = blockIdx.y * 32;
    const int txx = threadIdx.x, tyy = threadIdx.y;
    tile[tyy][txx] = A[(bx + tyy) * MATN + by + txx];
    __syncthreads();
    const int r = by + tyy, c = bx + txx;
    X[r * MATN + c] = scale * (A[r * MATN + c] - tile[txx][tyy]);
}

// out = cI*I + k1*x1 + k2*x2 + k3*x3 (+ k4*x4)
__global__ void poly_kernel(float* __restrict__ out,
                            const float* __restrict__ x1, const float* __restrict__ x2,
                            const float* __restrict__ x3, const float* __restrict__ x4,
                            float cI, float k1, float k2, float k3, float k4)
{
    const int idx = blockIdx.x * blockDim.x + threadIdx.x;
    if (idx >= NN) return;
    float v = k1 * x1[idx] + k2 * x2[idx] + k3 * x3[idx];
    if (x4) v += k4 * x4[idx];
    if (idx % (MATN + 1) == 0) v += cI;
    out[idx] = v;
}

// ---------------------------------------------------------------------------
// expm(A - A^T): scaling s=1 + degree-12 Taylor (Paterson-Stockmeyer)
// ---------------------------------------------------------------------------
extern "C" void kernel_launch(void* const* d_in, const int* in_sizes, int n_in,
                              void* d_out, int out_size)
{
    const float* A = (const float*)d_in[0];
    float* out = (float*)d_out;

    float* fbase = nullptr;
    cudaGetSymbolAddress((void**)&fbase, g_f);
    float* X  = fbase + 0 * (size_t)NN;
    float* X2 = fbase + 1 * (size_t)NN;
    float* X3 = fbase + 2 * (size_t)NN;
    float* X4 = fbase + 3 * (size_t)NN;
    float* T1 = fbase + 4 * (size_t)NN;
    float* T2 = fbase + 5 * (size_t)NN;
    float* B1 = fbase + 6 * (size_t)NN;

    unsigned char* pbase = nullptr;
    cudaGetSymbolAddress((void**)&pbase, g_pk);
    unsigned char* P0 = pbase + 0 * PK_BYTES;
    unsigned char* P1 = pbase + 1 * PK_BYTES;
    unsigned char* P2 = pbase + 2 * PK_BYTES;
    unsigned char* P3 = pbase + 3 * PK_BYTES;

    cudaFuncSetAttribute(gemm_bf16, cudaFuncAttributeMaxDynamicSharedMemorySize, SMEM_BYTES);

    const float c2  = 1.0f / 2.0f,       c3  = 1.0f / 6.0f;
    const float c4  = 1.0f / 24.0f,      c5  = 1.0f / 120.0f;
    const float c6  = 1.0f / 720.0f,     c7  = 1.0f / 5040.0f;
    const float c8  = 1.0f / 40320.0f,   c9  = 1.0f / 362880.0f;
    const float c10 = 1.0f / 3628800.0f, c11 = 1.0f / 39916800.0f;
    const float c12 = 1.0f / 479001600.0f;

    const dim3 gGrid(MATN / TILE_N, MATN / TILE_M);   // (16,16)
    const dim3 tGrid(MATN / 32, MATN / 32);
    const dim3 t32(32, 32);
    const int  pkBlocks = NN / 256;

    // X = (A - A^T)/2
    skew_kernel<<<tGrid, t32>>>(A, X, 0.5f);
    pack_L<<<pkBlocks, 256>>>(X, P0);
    pack_R<<<tGrid, t32>>>(X, P1);
    // X2 = X @ X
    gemm_bf16<<<gGrid, 288, SMEM_BYTES>>>(P0, P1, nullptr, X2);
    pack_L<<<pkBlocks, 256>>>(X2, P2);
    // X3 = X2 @ X
    gemm_bf16<<<gGrid, 288, SMEM_BYTES>>>(P2, P1, nullptr, X3);
    pack_R<<<tGrid, t32>>>(X2, P3);
    // X4 = X2 @ X2
    gemm_bf16<<<gGrid, 288, SMEM_BYTES>>>(P2, P3, nullptr, X4);
    pack_R<<<tGrid, t32>>>(X4, P0);
    // T1 = c8 I + c9 X + c10 X2 + c11 X3 + c12 X4
    poly_kernel<<<pkBlocks, 256>>>(T1, X, X2, X3, X4, c8, c9, c10, c11, c12);
    pack_L<<<pkBlocks, 256>>>(T1, P1);
    // B1 = c4 I + c5 X + c6 X2 + c7 X3
    poly_kernel<<<pkBlocks, 256>>>(B1, X, X2, X3, nullptr, c4, c5, c6, c7, 0.0f);
    // T2 = T1 @ X4 + B1
    gemm_bf16<<<gGrid, 288, SMEM_BYTES>>>(P1, P0, B1, T2);
    pack_L<<<pkBlocks, 256>>>(T2, P2);
    // B0 = I + X + c2 X2 + c3 X3   (into T1)
    poly_kernel<<<pkBlocks, 256>>>(T1, X, X2, X3, nullptr, 1.0f, 1.0f, c2, c3, 0.0f);
    // V = T2 @ X4 + B0   (into B1)
    gemm_bf16<<<gGrid, 288, SMEM_BYTES>>>(P2, P0, T1, B1);
    pack_L<<<pkBlocks, 256>>>(B1, P1);
    pack_R<<<tGrid, t32>>>(B1, P3);
    // out = V @ V
    gemm_bf16<<<gGrid, 288, SMEM_BYTES>>>(P1, P3, nullptr, out);
}

// round 8
// speedup vs baseline: 4.6172x; 1.3211x over previous
#include <cuda_runtime.h>
#include <cuda_bf16.h>
#include <cstdint>

#define MATN 2048
#define NN (MATN * MATN)
#define KP   6144                 // packed K = 3 * 2048 (bf16x3 split)
#define KC   64                   // K per stage
#define NSTAGE_ITERS (KP / KC)    // 96
#define STAGES 4
#define TILE_M 128
#define TILE_N 128

#define A_STG_BYTES (TILE_M * 128)   // 16384
#define B_STG_BYTES (TILE_N * 128)   // 16384

#define OFF_FULL   0
#define OFF_EMPTY  32
#define OFF_A      1024
#define OFF_B      (OFF_A + STAGES * A_STG_BYTES)
#define SMEM_BYTES (OFF_B + STAGES * B_STG_BYTES)      // 132096

#define PK_BYTES ((size_t)MATN * KP * 2)   // 25165824

// ---------------------------------------------------------------------------
// Scratch: 4 fp32 mats (X,X2,X3,X4) + 7 packed bf16 operand images
// ---------------------------------------------------------------------------
__device__ float g_f[4][NN];
__device__ __align__(128) unsigned char g_pk[7][PK_BYTES];

// ---------------------------------------------------------------------------
// PTX helpers (compute_103-safe)
// ---------------------------------------------------------------------------
__device__ __forceinline__ uint32_t smem_u32(const void* p) {
    uint32_t a;
    asm("{ .reg .u64 t; cvta.to.shared.u64 t, %1; cvt.u32.u64 %0, t; }" : "=r"(a) : "l"(p));
    return a;
}

#define MBAR_INIT(addr, cnt) \
    asm volatile("mbarrier.init.shared.b64 [%0], %1;" :: "r"(addr), "r"(cnt) : "memory")
#define MBAR_EXPECT_TX(addr, bytes) \
    asm volatile("mbarrier.arrive.expect_tx.shared.b64 _, [%0], %1;" :: "r"(addr), "r"(bytes) : "memory")
#define MBAR_ARRIVE(addr) \
    asm volatile("mbarrier.arrive.shared.b64 _, [%0];" :: "r"(addr) : "memory")

#define MBAR_WAIT(addr, ph) do {                                            \
    uint32_t _m = (addr), _p = (ph), _d;                                    \
    asm volatile("{\n\t.reg .pred p;\n\t"                                   \
        "mbarrier.try_wait.parity.acquire.cta.shared::cta.b64 p, [%1], %2;\n\t" \
        "selp.b32 %0, 1, 0, p;\n\t}"                                        \
        : "=r"(_d) : "r"(_m), "r"(_p) : "memory");                          \
    if (!_d) {                                                              \
        asm volatile("{\n\t.reg .pred P1;\n\t"                              \
            "WL_%=:\n\t"                                                    \
            "mbarrier.try_wait.parity.acquire.cta.shared::cta.b64 P1, [%0], %1, 0x989680;\n\t" \
            "@P1 bra.uni WD_%=;\n\t"                                        \
            "bra.uni WL_%=;\n\t"                                            \
            "WD_%=:\n\t}" :: "r"(_m), "r"(_p) : "memory");                  \
    }                                                                       \
} while (0)

__device__ __forceinline__ void bulk_g2s(uint32_t dst, const void* src, uint32_t bytes, uint32_t mbar) {
    asm volatile(
        "cp.async.bulk.shared::cluster.global.mbarrier::complete_tx::bytes [%0], [%1], %2, [%3];"
        :: "r"(dst), "l"(src), "r"(bytes), "r"(mbar) : "memory");
}

__device__ __forceinline__ void ldsm_x4(uint32_t* r, uint32_t addr) {
    asm volatile("ldmatrix.sync.aligned.m8n8.x4.shared.b16 {%0,%1,%2,%3}, [%4];"
                 : "=r"(r[0]), "=r"(r[1]), "=r"(r[2]), "=r"(r[3]) : "r"(addr));
}

__device__ __forceinline__ void mma_bf16(float* c, const uint32_t* a, const uint32_t* b) {
    asm volatile(
        "mma.sync.aligned.m16n8k16.row.col.f32.bf16.bf16.f32 "
        "{%0,%1,%2,%3}, {%4,%5,%6,%7}, {%8,%9}, {%0,%1,%2,%3};"
        : "+f"(c[0]), "+f"(c[1]), "+f"(c[2]), "+f"(c[3])
        : "r"(a[0]), "r"(a[1]), "r"(a[2]), "r"(a[3]), "r"(b[0]), "r"(b[1]));
}

// ---------------------------------------------------------------------------
// Packed-image pair store: value pair (v0,v1) at (row, col/col+1), col even.
// Layout: 16KB blocks [rowblk rb][kstage ks], SW128-swizzled 128x64 bf16.
// Left seg order  [h|h|l]; Right seg order [h;l;h].
// ---------------------------------------------------------------------------
__device__ __forceinline__ void pk_store_pair(unsigned char* __restrict__ base,
                                              int row, int col, float v0, float v1, bool isR)
{
    __nv_bfloat162 h2 = __floats2bfloat162_rn(v0, v1);
    float r0 = v0 - __bfloat162float(__low2bfloat16(h2));
    float r1 = v1 - __bfloat162float(__high2bfloat16(h2));
    __nv_bfloat162 l2 = __floats2bfloat162_rn(r0, r1);
    const uint32_t hh = reinterpret_cast<uint32_t&>(h2);
    const uint32_t ll = reinterpret_cast<uint32_t&>(l2);
    const int rb = row >> 7, rl = row & 127;
#pragma unroll
    for (int seg = 0; seg < 3; ++seg) {
        const int kcol = seg * 2048 + col;
        const int ks = kcol >> 6, cl = kcol & 63;
        uint32_t off = (uint32_t)rl * 128 + ((cl >> 3) << 4);
        off ^= (off >> 3) & 0x70;
        const size_t a = ((size_t)(rb * NSTAGE_ITERS + ks) << 14) + off + ((cl & 7) << 1);
        const uint32_t val = isR ? (seg == 1 ? ll : hh) : (seg == 2 ? ll : hh);
        *(uint32_t*)(base + a) = val;
    }
}

// ---------------------------------------------------------------------------
// GEMM: acc = Ap @ Bp^T (bf16x3 packed, fp32 acc), then epilogue:
//   if cx1: acc += cI*I + k1*cx1 + k2*cx2 + k3*cx3
//   if D:   store fp32
//   if PL:  store left-pack image   (row-major)
//   if PR:  store right-pack image  (valid: output symmetric)
// ---------------------------------------------------------------------------
__global__ void __launch_bounds__(288, 1)
gemm_bf16(const unsigned char* __restrict__ Ap, const unsigned char* __restrict__ Bp,
          const float* __restrict__ cx1, const float* __restrict__ cx2,
          const float* __restrict__ cx3,
          float cI, float k1, float k2, float k3,
          float* __restrict__ D,
          unsigned char* __restrict__ PL, unsigned char* __restrict__ PR)
{
    extern __shared__ __align__(1024) unsigned char smem[];
    const uint32_t sb = smem_u32(smem);
    const int tid = threadIdx.x;
    const int wid = tid >> 5;
    const int lid = tid & 31;
    const int nt = blockIdx.x;
    const int mt = blockIdx.y;

    if (tid == 0) {
        for (int s = 0; s < STAGES; s++) {
            MBAR_INIT(sb + OFF_FULL  + s * 8, 1);
            MBAR_INIT(sb + OFF_EMPTY + s * 8, 8);
        }
    }
    __syncthreads();

    if (wid == 8) {
        if (lid == 0) {
            const unsigned char* srcA = Ap + (size_t)mt * NSTAGE_ITERS * A_STG_BYTES;
            const unsigned char* srcB = Bp + (size_t)nt * NSTAGE_ITERS * B_STG_BYTES;
            int st = 0, ph = 1;
            for (int ks = 0; ks < NSTAGE_ITERS; ++ks) {
                MBAR_WAIT(sb + OFF_EMPTY + st * 8, ph);
                MBAR_EXPECT_TX(sb + OFF_FULL + st * 8, A_STG_BYTES + B_STG_BYTES);
                bulk_g2s(sb + OFF_A + st * A_STG_BYTES, srcA + (size_t)ks * A_STG_BYTES,
                         A_STG_BYTES, sb + OFF_FULL + st * 8);
                bulk_g2s(sb + OFF_B + st * B_STG_BYTES, srcB + (size_t)ks * B_STG_BYTES,
                         B_STG_BYTES, sb + OFF_FULL + st * 8);
                if (++st == STAGES) { st = 0; ph ^= 1; }
            }
        }
        return;
    }

    const int mb = (wid >> 1) * 32;
    const int nb = (wid & 1) * 64;

    const int rA   = mb + (lid & 15);
    const int chA  = (lid >> 4);
    const uint32_t xorA = (rA & 7) << 4;
    const int rB   = nb + (lid & 7) + ((lid >> 4) << 3);
    const int chB  = (lid >> 3) & 1;
    const uint32_t xorB = (rB & 7) << 4;

    float acc[2][8][4];
#pragma unroll
    for (int mi = 0; mi < 2; mi++)
#pragma unroll
        for (int j = 0; j < 8; j++)
#pragma unroll
            for (int q = 0; q < 4; q++) acc[mi][j][q] = 0.0f;

    int st = 0, ph = 0;
#pragma unroll 1
    for (int ks = 0; ks < NSTAGE_ITERS; ++ks) {
        MBAR_WAIT(sb + OFF_FULL + st * 8, ph);
        const uint32_t baseA = sb + OFF_A + st * A_STG_BYTES + (uint32_t)rA * 128;
        const uint32_t baseB = sb + OFF_B + st * B_STG_BYTES + (uint32_t)rB * 128;

#pragma unroll
        for (int kk = 0; kk < 4; ++kk) {
            uint32_t a[2][4];
            const uint32_t kcA = (uint32_t)(kk * 2 + chA) * 16 ^ xorA;
            ldsm_x4(a[0], baseA + kcA);
            ldsm_x4(a[1], baseA + 2048 + kcA);

            uint32_t b[4][4];
            const uint32_t kcB = (uint32_t)(kk * 2 + chB) * 16 ^ xorB;
#pragma unroll
            for (int jj = 0; jj < 4; ++jj)
                ldsm_x4(b[jj], baseB + (uint32_t)jj * 2048 + kcB);

#pragma unroll
            for (int mi = 0; mi < 2; ++mi)
#pragma unroll
                for (int j = 0; j < 8; ++j)
                    mma_bf16(acc[mi][j], a[mi], &b[j >> 1][(j & 1) * 2]);
        }

        if (lid == 0) MBAR_ARRIVE(sb + OFF_EMPTY + st * 8);
        if (++st == STAGES) { st = 0; ph ^= 1; }
    }

    // ---- epilogue ----
    const int g = lid >> 2, t = lid & 3;
    const int rowBase = mt * TILE_M + mb;
    const int colBase = nt * TILE_N + nb;
#pragma unroll
    for (int mi = 0; mi < 2; ++mi) {
#pragma unroll
        for (int half = 0; half < 2; ++half) {
            const int r0 = rowBase + mi * 16 + half * 8 + g;
#pragma unroll
            for (int j = 0; j < 8; ++j) {
                const int c = colBase + j * 8 + t * 2;
                float v0 = acc[mi][j][half * 2 + 0];
                float v1 = acc[mi][j][half * 2 + 1];
                if (cx1) {
                    const size_t e = (size_t)r0 * MATN + c;
                    float2 a1 = *(const float2*)(cx1 + e);
                    float2 a2 = *(const float2*)(cx2 + e);
                    float2 a3 = *(const float2*)(cx3 + e);
                    v0 += k1 * a1.x + k2 * a2.x + k3 * a3.x;
                    v1 += k1 * a1.y + k2 * a2.y + k3 * a3.y;
                    if (r0 == c)     v0 += cI;
                    if (r0 == c + 1) v1 += cI;
                }
                if (D) *(float2*)(D + (size_t)r0 * MATN + c) = make_float2(v0, v1);
                if (PL) pk_store_pair(PL, r0, c, v0, v1, false);
                if (PR) pk_store_pair(PR, r0, c, v0, v1, true);
            }
        }
    }
}

// ---------------------------------------------------------------------------
// skew_pack: X = A - A^T (fp32) + fused PL(X) and PR(X) (= rows of -X, since
// X^T = -X). Block = 32x32 tile, threads (16,32), 2 cols per thread.
// ---------------------------------------------------------------------------
__global__ void skew_pack(const float* __restrict__ A, float* __restrict__ X,
                          unsigned char* __restrict__ PL, unsigned char* __restrict__ PR)
{
    __shared__ float tT[32][33];
    const int rblk = blockIdx.y * 32, cblk = blockIdx.x * 32;
    const int tfl = threadIdx.y * 16 + threadIdx.x;   // 0..511
#pragma unroll
    for (int e = tfl; e < 1024; e += 512) {
        const int u = e >> 5, v = e & 31;
        tT[u][v] = A[(size_t)(cblk + u) * MATN + rblk + v];
    }
    __syncthreads();
    const int r = rblk + threadIdx.y;
    const int c0 = cblk + threadIdx.x * 2;
    float2 av = *(const float2*)(A + (size_t)r * MATN + c0);
    const float x0 = av.x - tT[threadIdx.x * 2][threadIdx.y];
    const float x1 = av.y - tT[threadIdx.x * 2 + 1][threadIdx.y];
    *(float2*)(X + (size_t)r * MATN + c0) = make_float2(x0, x1);
    pk_store_pair(PL, r, c0, x0, x1, false);
    pk_store_pair(PR, r, c0, -x0, -x1, true);
}

// ---------------------------------------------------------------------------
// poly_T: T = c8 I + c9 X + c10 X2 + c11 X3 + c12 X4 -> PL image only
// ---------------------------------------------------------------------------
__global__ void poly_T(const float* __restrict__ x1, const float* __restrict__ x2,
                       const float* __restrict__ x3, const float* __restrict__ x4,
                       unsigned char* __restrict__ PL,
                       float cI, float k1, float k2, float k3, float k4)
{
    const size_t i2 = ((size_t)blockIdx.x * blockDim.x + threadIdx.x) * 2;
    float2 a = *(const float2*)(x1 + i2);
    float2 b = *(const float2*)(x2 + i2);
    float2 c = *(const float2*)(x3 + i2);
    float2 d = *(const float2*)(x4 + i2);
    float v0 = k1 * a.x + k2 * b.x + k3 * c.x + k4 * d.x;
    float v1 = k1 * a.y + k2 * b.y + k3 * c.y + k4 * d.y;
    const int row = (int)(i2 >> 11), col = (int)(i2 & 2047);
    if (row == col)     v0 += cI;
    if (row == col + 1) v1 += cI;
    pk_store_pair(PL, row, col, v0, v1, false);
}

// ---------------------------------------------------------------------------
// expm(A - A^T): no scaling, degree-12 Taylor, Paterson-Stockmeyer q=4:
//   out = b0 + X4*(b1 + X4*b2), 5 GEMMs total, all packing fused.
// ---------------------------------------------------------------------------
extern "C" void kernel_launch(void* const* d_in, const int* in_sizes, int n_in,
                              void* d_out, int out_size)
{
    const float* A = (const float*)d_in[0];
    float* out = (float*)d_out;

    float* fbase = nullptr;
    cudaGetSymbolAddress((void**)&fbase, g_f);
    float* X  = fbase + 0 * (size_t)NN;
    float* X2 = fbase + 1 * (size_t)NN;
    float* X3 = fbase + 2 * (size_t)NN;
    float* X4 = fbase + 3 * (size_t)NN;

    unsigned char* pbase = nullptr;
    cudaGetSymbolAddress((void**)&pbase, g_pk);
    unsigned char* PL_X  = pbase + 0 * PK_BYTES;
    unsigned char* PR_X  = pbase + 1 * PK_BYTES;
    unsigned char* PL_X2 = pbase + 2 * PK_BYTES;
    unsigned char* PR_X2 = pbase + 3 * PK_BYTES;
    unsigned char* PR_X4 = pbase + 4 * PK_BYTES;
    unsigned char* PL_T  = pbase + 5 * PK_BYTES;
    unsigned char* PL_G1 = pbase + 6 * PK_BYTES;

    cudaFuncSetAttribute(gemm_bf16, cudaFuncAttributeMaxDynamicSharedMemorySize, SMEM_BYTES);

    const float c2  = 1.0f / 2.0f,       c3  = 1.0f / 6.0f;
    const float c4  = 1.0f / 24.0f,      c5  = 1.0f / 120.0f;
    const float c6  = 1.0f / 720.0f,     c7  = 1.0f / 5040.0f;
    const float c8  = 1.0f / 40320.0f,   c9  = 1.0f / 362880.0f;
    const float c10 = 1.0f / 3628800.0f, c11 = 1.0f / 39916800.0f;
    const float c12 = 1.0f / 479001600.0f;

    const dim3 gGrid(MATN / TILE_N, MATN / TILE_M);   // (16,16)
    const dim3 sGrid(MATN / 32, MATN / 32);

    // X = A - A^T, fused PL_X / PR_X
    skew_pack<<<sGrid, dim3(16, 32)>>>(A, X, PL_X, PR_X);
    // X2 = X @ X  (symmetric) -> fp32 + PL_X2 + PR_X2
    gemm_bf16<<<gGrid, 288, SMEM_BYTES>>>(PL_X, PR_X, nullptr, nullptr, nullptr,
                                          0, 0, 0, 0, X2, PL_X2, PR_X2);
    // X3 = X2 @ X -> fp32 only
    gemm_bf16<<<gGrid, 288, SMEM_BYTES>>>(PL_X2, PR_X, nullptr, nullptr, nullptr,
                                          0, 0, 0, 0, X3, nullptr, nullptr);
    // X4 = X2 @ X2 (symmetric) -> fp32 + PR_X4
    gemm_bf16<<<gGrid, 288, SMEM_BYTES>>>(PL_X2, PR_X2, nullptr, nullptr, nullptr,
                                          0, 0, 0, 0, X4, nullptr, PR_X4);
    // T = b2 -> PL_T only
    poly_T<<<NN / 512, 256>>>(X, X2, X3, X4, PL_T, c8, c9, c10, c11, c12);
    // G1 = T @ X4 + b1 -> PL_G1 only (b1 = c4 I + c5 X + c6 X2 + c7 X3)
    gemm_bf16<<<gGrid, 288, SMEM_BYTES>>>(PL_T, PR_X4, X, X2, X3,
                                          c4, c5, c6, c7, nullptr, PL_G1, nullptr);
    // out = G1 @ X4 + b0  (b0 = I + X + c2 X2 + c3 X3)
    gemm_bf16<<<gGrid, 288, SMEM_BYTES>>>(PL_G1, PR_X4, X, X2, X3,
                                          1.0f, 1.0f, c2, c3, out, nullptr, nullptr);
}

// round 10
// speedup vs baseline: 7.3472x; 1.5913x over previous
#include <cuda_runtime.h>
#include <cuda_bf16.h>
#include <cstdint>
#include <cmath>

#define MATN 2048
#define NN (MATN * MATN)
#define KP   6144                 // packed K = 3 * 2048 (bf16x3 split)
#define KC   64
#define NSTAGE_ITERS (KP / KC)    // 96
#define STAGES 4
#define TILE_M 128
#define TILE_N 128

#define A_STG_BYTES (TILE_M * 128)
#define B_STG_BYTES (TILE_N * 128)

#define OFF_FULL   0
#define OFF_EMPTY  32
#define OFF_A      1024
#define OFF_B      (OFF_A + STAGES * A_STG_BYTES)
#define SMEM_BYTES (OFF_B + STAGES * B_STG_BYTES)      // 132096

#define PK_BYTES ((size_t)MATN * KP * 2)   // 25165824

// ---------------------------------------------------------------------------
// Scratch: 3 fp32 mats (X, X2, Y1) + 4 packed bf16 operand images
// ---------------------------------------------------------------------------
__device__ float g_f[3][NN];
__device__ __align__(128) unsigned char g_pk[4][PK_BYTES];

// ---------------------------------------------------------------------------
// PTX helpers (compute_103-safe)
// ---------------------------------------------------------------------------
__device__ __forceinline__ uint32_t smem_u32(const void* p) {
    uint32_t a;
    asm("{ .reg .u64 t; cvta.to.shared.u64 t, %1; cvt.u32.u64 %0, t; }" : "=r"(a) : "l"(p));
    return a;
}

#define MBAR_INIT(addr, cnt) \
    asm volatile("mbarrier.init.shared.b64 [%0], %1;" :: "r"(addr), "r"(cnt) : "memory")
#define MBAR_EXPECT_TX(addr, bytes) \
    asm volatile("mbarrier.arrive.expect_tx.shared.b64 _, [%0], %1;" :: "r"(addr), "r"(bytes) : "memory")
#define MBAR_ARRIVE(addr) \
    asm volatile("mbarrier.arrive.shared.b64 _, [%0];" :: "r"(addr) : "memory")

#define MBAR_WAIT(addr, ph) do {                                            \
    uint32_t _m = (addr), _p = (ph), _d;                                    \
    asm volatile("{\n\t.reg .pred p;\n\t"                                   \
        "mbarrier.try_wait.parity.acquire.cta.shared::cta.b64 p, [%1], %2;\n\t" \
        "selp.b32 %0, 1, 0, p;\n\t}"                                        \
        : "=r"(_d) : "r"(_m), "r"(_p) : "memory");                          \
    if (!_d) {                                                              \
        asm volatile("{\n\t.reg .pred P1;\n\t"                              \
            "WL_%=:\n\t"                                                    \
            "mbarrier.try_wait.parity.acquire.cta.shared::cta.b64 P1, [%0], %1, 0x989680;\n\t" \
            "@P1 bra.uni WD_%=;\n\t"                                        \
            "bra.uni WL_%=;\n\t"                                            \
            "WD_%=:\n\t}" :: "r"(_m), "r"(_p) : "memory");                  \
    }                                                                       \
} while (0)

__device__ __forceinline__ void bulk_g2s(uint32_t dst, const void* src, uint32_t bytes, uint32_t mbar) {
    asm volatile(
        "cp.async.bulk.shared::cluster.global.mbarrier::complete_tx::bytes [%0], [%1], %2, [%3];"
        :: "r"(dst), "l"(src), "r"(bytes), "r"(mbar) : "memory");
}

__device__ __forceinline__ void ldsm_x4(uint32_t* r, uint32_t addr) {
    asm volatile("ldmatrix.sync.aligned.m8n8.x4.shared.b16 {%0,%1,%2,%3}, [%4];"
                 : "=r"(r[0]), "=r"(r[1]), "=r"(r[2]), "=r"(r[3]) : "r"(addr));
}

__device__ __forceinline__ void mma_bf16(float* c, const uint32_t* a, const uint32_t* b) {
    asm volatile(
        "mma.sync.aligned.m16n8k16.row.col.f32.bf16.bf16.f32 "
        "{%0,%1,%2,%3}, {%4,%5,%6,%7}, {%8,%9}, {%0,%1,%2,%3};"
        : "+f"(c[0]), "+f"(c[1]), "+f"(c[2]), "+f"(c[3])
        : "r"(a[0]), "r"(a[1]), "r"(a[2]), "r"(a[3]), "r"(b[0]), "r"(b[1]));
}

// ---------------------------------------------------------------------------
// Packed-image pair store (bf16x3 split). Left segs [h|h|l]; right [h;l;h].
// pk_store_pair(PR, r, c, val): val is interpreted as B[c, r] of the right
// operand (image row r = operand column r).
// ---------------------------------------------------------------------------
__device__ __forceinline__ void pk_store_pair(unsigned char* __restrict__ base,
                                              int row, int col, float v0, float v1, bool isR)
{
    __nv_bfloat162 h2 = __floats2bfloat162_rn(v0, v1);
    float r0 = v0 - __bfloat162float(__low2bfloat16(h2));
    float r1 = v1 - __bfloat162float(__high2bfloat16(h2));
    __nv_bfloat162 l2 = __floats2bfloat162_rn(r0, r1);
    const uint32_t hh = reinterpret_cast<uint32_t&>(h2);
    const uint32_t ll = reinterpret_cast<uint32_t&>(l2);
    const int rb = row >> 7, rl = row & 127;
#pragma unroll
    for (int seg = 0; seg < 3; ++seg) {
        const int kcol = seg * 2048 + col;
        const int ks = kcol >> 6, cl = kcol & 63;
        uint32_t off = (uint32_t)rl * 128 + ((cl >> 3) << 4);
        off ^= (off >> 3) & 0x70;
        const size_t a = ((size_t)(rb * NSTAGE_ITERS + ks) << 14) + off + ((cl & 7) << 1);
        const uint32_t val = isR ? (seg == 1 ? ll : hh) : (seg == 2 ? ll : hh);
        *(uint32_t*)(base + a) = val;
    }
}

// ---------------------------------------------------------------------------
// GEMM: acc = Ap @ Bp^T (bf16x3 packed, fp32 acc). Epilogue options:
//   if e1:  acc += cI*I + k1*e1 + k2*e2 + k3*e3   (3-matrix combine)
//   if D:   store fp32
//   if PL:  left-pack image of result
//   if PR:  right-pack image of (prA*result + prB*Xw)   [Xw read from gmem]
// ---------------------------------------------------------------------------
__global__ void __launch_bounds__(288, 1)
gemm_bf16(const unsigned char* __restrict__ Ap, const unsigned char* __restrict__ Bp,
          const float* __restrict__ e1, const float* __restrict__ e2,
          const float* __restrict__ e3,
          float cI, float k1, float k2, float k3,
          float* __restrict__ D,
          unsigned char* __restrict__ PL, unsigned char* __restrict__ PR,
          const float* __restrict__ Xw, float prA, float prB)
{
    extern __shared__ __align__(1024) unsigned char smem[];
    const uint32_t sb = smem_u32(smem);
    const int tid = threadIdx.x;
    const int wid = tid >> 5;
    const int lid = tid & 31;
    const int nt = blockIdx.x;
    const int mt = blockIdx.y;

    if (tid == 0) {
        for (int s = 0; s < STAGES; s++) {
            MBAR_INIT(sb + OFF_FULL  + s * 8, 1);
            MBAR_INIT(sb + OFF_EMPTY + s * 8, 8);
        }
    }
    __syncthreads();

    if (wid == 8) {
        if (lid == 0) {
            const unsigned char* srcA = Ap + (size_t)mt * NSTAGE_ITERS * A_STG_BYTES;
            const unsigned char* srcB = Bp + (size_t)nt * NSTAGE_ITERS * B_STG_BYTES;
            int st = 0, ph = 1;
            for (int ks = 0; ks < NSTAGE_ITERS; ++ks) {
                MBAR_WAIT(sb + OFF_EMPTY + st * 8, ph);
                MBAR_EXPECT_TX(sb + OFF_FULL + st * 8, A_STG_BYTES + B_STG_BYTES);
                bulk_g2s(sb + OFF_A + st * A_STG_BYTES, srcA + (size_t)ks * A_STG_BYTES,
                         A_STG_BYTES, sb + OFF_FULL + st * 8);
                bulk_g2s(sb + OFF_B + st * B_STG_BYTES, srcB + (size_t)ks * B_STG_BYTES,
                         B_STG_BYTES, sb + OFF_FULL + st * 8);
                if (++st == STAGES) { st = 0; ph ^= 1; }
            }
        }
        return;
    }

    const int mb = (wid >> 1) * 32;
    const int nb = (wid & 1) * 64;

    const int rA   = mb + (lid & 15);
    const int chA  = (lid >> 4);
    const uint32_t xorA = (rA & 7) << 4;
    const int rB   = nb + (lid & 7) + ((lid >> 4) << 3);
    const int chB  = (lid >> 3) & 1;
    const uint32_t xorB = (rB & 7) << 4;

    float acc[2][8][4];
#pragma unroll
    for (int mi = 0; mi < 2; mi++)
#pragma unroll
        for (int j = 0; j < 8; j++)
#pragma unroll
            for (int q = 0; q < 4; q++) acc[mi][j][q] = 0.0f;

    int st = 0, ph = 0;
#pragma unroll 1
    for (int ks = 0; ks < NSTAGE_ITERS; ++ks) {
        MBAR_WAIT(sb + OFF_FULL + st * 8, ph);
        const uint32_t baseA = sb + OFF_A + st * A_STG_BYTES + (uint32_t)rA * 128;
        const uint32_t baseB = sb + OFF_B + st * B_STG_BYTES + (uint32_t)rB * 128;

#pragma unroll
        for (int kk = 0; kk < 4; ++kk) {
            uint32_t a[2][4];
            const uint32_t kcA = (uint32_t)(kk * 2 + chA) * 16 ^ xorA;
            ldsm_x4(a[0], baseA + kcA);
            ldsm_x4(a[1], baseA + 2048 + kcA);

            uint32_t b[4][4];
            const uint32_t kcB = (uint32_t)(kk * 2 + chB) * 16 ^ xorB;
#pragma unroll
            for (int jj = 0; jj < 4; ++jj)
                ldsm_x4(b[jj], baseB + (uint32_t)jj * 2048 + kcB);

#pragma unroll
            for (int mi = 0; mi < 2; ++mi)
#pragma unroll
                for (int j = 0; j < 8; ++j)
                    mma_bf16(acc[mi][j], a[mi], &b[j >> 1][(j & 1) * 2]);
        }

        if (lid == 0) MBAR_ARRIVE(sb + OFF_EMPTY + st * 8);
        if (++st == STAGES) { st = 0; ph ^= 1; }
    }

    // ---- epilogue ----
    const int g = lid >> 2, t = lid & 3;
    const int rowBase = mt * TILE_M + mb;
    const int colBase = nt * TILE_N + nb;
#pragma unroll
    for (int mi = 0; mi < 2; ++mi) {
#pragma unroll
        for (int half = 0; half < 2; ++half) {
            const int r0 = rowBase + mi * 16 + half * 8 + g;
#pragma unroll
            for (int j = 0; j < 8; ++j) {
                const int c = colBase + j * 8 + t * 2;
                const size_t e = (size_t)r0 * MATN + c;
                float v0 = acc[mi][j][half * 2 + 0];
                float v1 = acc[mi][j][half * 2 + 1];
                if (e1) {
                    float2 a1 = *(const float2*)(e1 + e);
                    float2 a2 = *(const float2*)(e2 + e);
                    float2 a3 = *(const float2*)(e3 + e);
                    v0 += k1 * a1.x + k2 * a2.x + k3 * a3.x;
                    v1 += k1 * a1.y + k2 * a2.y + k3 * a3.y;
                    if (r0 == c)     v0 += cI;
                    if (r0 == c + 1) v1 += cI;
                }
                if (D) *(float2*)(D + e) = make_float2(v0, v1);
                if (PL) pk_store_pair(PL, r0, c, v0, v1, false);
                if (PR) {
                    float2 xw = *(const float2*)(Xw + e);
                    pk_store_pair(PR, r0, c, prA * v0 + prB * xw.x,
                                              prA * v1 + prB * xw.y, true);
                }
            }
        }
    }
}

// ---------------------------------------------------------------------------
// skew_pack: X = A - A^T (fp32) + PL(X) + PR(X) (X antisym: X^T = -X)
// ---------------------------------------------------------------------------
__global__ void skew_pack(const float* __restrict__ A, float* __restrict__ X,
                          unsigned char* __restrict__ PL, unsigned char* __restrict__ PR)
{
    __shared__ float tT[32][33];
    const int rblk = blockIdx.y * 32, cblk = blockIdx.x * 32;
    const int tfl = threadIdx.y * 16 + threadIdx.x;
#pragma unroll
    for (int e = tfl; e < 1024; e += 512) {
        const int u = e >> 5, v = e & 31;
        tT[u][v] = A[(size_t)(cblk + u) * MATN + rblk + v];
    }
    __syncthreads();
    const int r = rblk + threadIdx.y;
    const int c0 = cblk + threadIdx.x * 2;
    float2 av = *(const float2*)(A + (size_t)r * MATN + c0);
    const float x0 = av.x - tT[threadIdx.x * 2][threadIdx.y];
    const float x1 = av.y - tT[threadIdx.x * 2 + 1][threadIdx.y];
    *(float2*)(X + (size_t)r * MATN + c0) = make_float2(x0, x1);
    pk_store_pair(PL, r, c0, x0, x1, false);
    pk_store_pair(PR, r, c0, -x0, -x1, true);
}

// ---------------------------------------------------------------------------
// prep: from Y1 (=c1X^4+c2X^3), X2, X build
//   PL_u : u = Y1 + P*X2 + R*X            (left image, row-major)
//   PR_v : v = Y1 + S*X; need v[c,r] = Y1^T[r,c] - S*X[r,c]  (Y1^T via smem)
// ---------------------------------------------------------------------------
__global__ void prep_uv(const float* __restrict__ Y1, const float* __restrict__ X2,
                        const float* __restrict__ X,
                        unsigned char* __restrict__ PLu, unsigned char* __restrict__ PRv,
                        float Pc, float Rc, float Sc)
{
    __shared__ float tT[32][33];
    const int rblk = blockIdx.y * 32, cblk = blockIdx.x * 32;
    const int tfl = threadIdx.y * 16 + threadIdx.x;
#pragma unroll
    for (int e = tfl; e < 1024; e += 512) {
        const int u = e >> 5, v = e & 31;
        tT[u][v] = Y1[(size_t)(cblk + u) * MATN + rblk + v];   // Y1^T tile
    }
    __syncthreads();
    const int r = rblk + threadIdx.y;
    const int c0 = cblk + threadIdx.x * 2;
    const size_t eidx = (size_t)r * MATN + c0;
    float2 y  = *(const float2*)(Y1 + eidx);
    float2 x2 = *(const float2*)(X2 + eidx);
    float2 x  = *(const float2*)(X  + eidx);
    // u = Y1 + P*X2 + R*X
    pk_store_pair(PLu, r, c0, y.x + Pc * x2.x + Rc * x.x,
                              y.y + Pc * x2.y + Rc * x.y, false);
    // v[c,r] = Y1[c,r] + S*X[c,r] = Y1^T[r,c] - S*X[r,c]
    const float yt0 = tT[threadIdx.x * 2][threadIdx.y];
    const float yt1 = tT[threadIdx.x * 2 + 1][threadIdx.y];
    pk_store_pair(PRv, r, c0, yt0 - Sc * x.x, yt1 - Sc * x.y, true);
}

// ---------------------------------------------------------------------------
// expm(A - A^T), degree-8 Taylor via 3-product scheme:
//   X2 = X^2
//   Y1 = X2 @ (c1*X2 + c2*X)
//   out = (Y1 + P*X2 + R*X)(Y1 + S*X) + f1*Y1 + f2*X2 + X + I
// ---------------------------------------------------------------------------
extern "C" void kernel_launch(void* const* d_in, const int* in_sizes, int n_in,
                              void* d_out, int out_size)
{
    const float* A = (const float*)d_in[0];
    float* out = (float*)d_out;

    float* fbase = nullptr;
    cudaGetSymbolAddress((void**)&fbase, g_f);
    float* X  = fbase + 0 * (size_t)NN;
    float* X2 = fbase + 1 * (size_t)NN;
    float* Y1 = fbase + 2 * (size_t)NN;

    unsigned char* pbase = nullptr;
    cudaGetSymbolAddress((void**)&pbase, g_pk);
    unsigned char* IMG0 = pbase + 0 * PK_BYTES;   // PL_X  -> PL_u
    unsigned char* IMG1 = pbase + 1 * PK_BYTES;   // PR_X  -> PR_v
    unsigned char* IMG2 = pbase + 2 * PK_BYTES;   // PL_X2
    unsigned char* IMG3 = pbase + 3 * PK_BYTES;   // PR_W

    cudaFuncSetAttribute(gemm_bf16, cudaFuncAttributeMaxDynamicSharedMemorySize, SMEM_BYTES);

    // degree-8 3-product coefficients (exact closed forms, double precision)
    const double c1d = 1.0 / sqrt(40320.0);
    const double c2d = 4.0 * c1d;
    const double Pd  = 40.0 * c1d;
    const double sd  = -11.0 / (25200.0 * c1d);
    const double Rd  = 88.0 * c1d - sd;
    const double Sd  = 88.0 * c1d + sd;
    const double f1d = (61.0 / 2520.0) / c1d;
    const double f2d = 0.5 - Rd * Sd;

    const float c1f = (float)c1d, c2f = (float)c2d;
    const float Pf = (float)Pd, Rf = (float)Rd, Sf = (float)Sd;
    const float f1f = (float)f1d, f2f = (float)f2d;

    const dim3 gGrid(MATN / TILE_N, MATN / TILE_M);   // (16,16)
    const dim3 sGrid(MATN / 32, MATN / 32);
    const dim3 sBlk(16, 32);

    // X = A - A^T  -> X fp32, PL_X (IMG0), PR_X (IMG1)
    skew_pack<<<sGrid, sBlk>>>(A, X, IMG0, IMG1);

    // GEMM1: X2 = X @ X  -> X2 fp32, PL_X2 (IMG2), PR_W (IMG3) with W = c1*X2 + c2*X
    gemm_bf16<<<gGrid, 288, SMEM_BYTES>>>(IMG0, IMG1, nullptr, nullptr, nullptr,
                                          0, 0, 0, 0, X2, IMG2, IMG3, X, c1f, -c2f);

    // GEMM2: Y1 = X2 @ W -> Y1 fp32 only
    gemm_bf16<<<gGrid, 288, SMEM_BYTES>>>(IMG2, IMG3, nullptr, nullptr, nullptr,
                                          0, 0, 0, 0, Y1, nullptr, nullptr, nullptr, 0, 0);

    // prep: PL_u (IMG0), PR_v (IMG1)
    prep_uv<<<sGrid, sBlk>>>(Y1, X2, X, IMG0, IMG1, Pf, Rf, Sf);

    // GEMM3: out = u @ v + I + 1*X + f2*X2 + f1*Y1
    gemm_bf16<<<gGrid, 288, SMEM_BYTES>>>(IMG0, IMG1, X, X2, Y1,
                                          1.0f, 1.0f, f2f, f1f, out,
                                          nullptr, nullptr, nullptr, 0, 0);
}

// round 12
// speedup vs baseline: 9.4763x; 1.2898x over previous
#include <cuda_runtime.h>
#include <cuda_bf16.h>
#include <cstdint>

#define MATN 2048
#define NN (MATN * MATN)
#define KP   6144                 // packed K = 3 * 2048 (bf16x3 split)
#define KC   64
#define NSTAGE_ITERS (KP / KC)    // 96
#define STAGES 4
#define TILE_M 128
#define TILE_N 128
#define NTILE (MATN / TILE_M)     // 16
#define NBLK  (NTILE * (NTILE + 1) / 2)   // 136 upper-triangle tiles

#define A_STG_BYTES (TILE_M * 128)
#define B_STG_BYTES (TILE_N * 128)

#define OFF_FULL   0
#define OFF_EMPTY  32
#define OFF_A      1024
#define OFF_B      (OFF_A + STAGES * A_STG_BYTES)
#define SMEM_BYTES (OFF_B + STAGES * B_STG_BYTES)      // 132096

#define PK_BYTES ((size_t)MATN * KP * 2)   // 25165824

// ---------------------------------------------------------------------------
// Scratch: 3 fp32 mats (Y, Y2, Y3; upper tiles only used) + 6 packed images
// ---------------------------------------------------------------------------
__device__ float g_f[3][NN];
__device__ __align__(128) unsigned char g_pk[6][PK_BYTES];

// ---------------------------------------------------------------------------
// PTX helpers (compute_103-safe)
// ---------------------------------------------------------------------------
__device__ __forceinline__ uint32_t smem_u32(const void* p) {
    uint32_t a;
    asm("{ .reg .u64 t; cvta.to.shared.u64 t, %1; cvt.u32.u64 %0, t; }" : "=r"(a) : "l"(p));
    return a;
}

#define MBAR_INIT(addr, cnt) \
    asm volatile("mbarrier.init.shared.b64 [%0], %1;" :: "r"(addr), "r"(cnt) : "memory")
#define MBAR_EXPECT_TX(addr, bytes) \
    asm volatile("mbarrier.arrive.expect_tx.shared.b64 _, [%0], %1;" :: "r"(addr), "r"(bytes) : "memory")
#define MBAR_ARRIVE(addr) \
    asm volatile("mbarrier.arrive.shared.b64 _, [%0];" :: "r"(addr) : "memory")

#define MBAR_WAIT(addr, ph) do {                                            \
    uint32_t _m = (addr), _p = (ph), _d;                                    \
    asm volatile("{\n\t.reg .pred p;\n\t"                                   \
        "mbarrier.try_wait.parity.acquire.cta.shared::cta.b64 p, [%1], %2;\n\t" \
        "selp.b32 %0, 1, 0, p;\n\t}"                                        \
        : "=r"(_d) : "r"(_m), "r"(_p) : "memory");                          \
    if (!_d) {                                                              \
        asm volatile("{\n\t.reg .pred P1;\n\t"                              \
            "WL_%=:\n\t"                                                    \
            "mbarrier.try_wait.parity.acquire.cta.shared::cta.b64 P1, [%0], %1, 0x989680;\n\t" \
            "@P1 bra.uni WD_%=;\n\t"                                        \
            "bra.uni WL_%=;\n\t"                                            \
            "WD_%=:\n\t}" :: "r"(_m), "r"(_p) : "memory");                  \
    }                                                                       \
} while (0)

__device__ __forceinline__ void bulk_g2s(uint32_t dst, const void* src, uint32_t bytes, uint32_t mbar) {
    asm volatile(
        "cp.async.bulk.shared::cluster.global.mbarrier::complete_tx::bytes [%0], [%1], %2, [%3];"
        :: "r"(dst), "l"(src), "r"(bytes), "r"(mbar) : "memory");
}

__device__ __forceinline__ void ldsm_x4(uint32_t* r, uint32_t addr) {
    asm volatile("ldmatrix.sync.aligned.m8n8.x4.shared.b16 {%0,%1,%2,%3}, [%4];"
                 : "=r"(r[0]), "=r"(r[1]), "=r"(r[2]), "=r"(r[3]) : "r"(addr));
}

__device__ __forceinline__ void mma_bf16(float* c, const uint32_t* a, const uint32_t* b) {
    asm volatile(
        "mma.sync.aligned.m16n8k16.row.col.f32.bf16.bf16.f32 "
        "{%0,%1,%2,%3}, {%4,%5,%6,%7}, {%8,%9}, {%0,%1,%2,%3};"
        : "+f"(c[0]), "+f"(c[1]), "+f"(c[2]), "+f"(c[3])
        : "r"(a[0]), "r"(a[1]), "r"(a[2]), "r"(a[3]), "r"(b[0]), "r"(b[1]));
}

// ---------------------------------------------------------------------------
// Packed-image stores (bf16x3 split). Left segs [h|h|l]; right segs [h;l;h].
// Image row = operand row (left) / operand column (right).
// ---------------------------------------------------------------------------
__device__ __forceinline__ void pk_store_pair(unsigned char* __restrict__ base,
                                              int row, int col, float v0, float v1, bool isR)
{
    __nv_bfloat162 h2 = __floats2bfloat162_rn(v0, v1);
    float r0 = v0 - __bfloat162float(__low2bfloat16(h2));
    float r1 = v1 - __bfloat162float(__high2bfloat16(h2));
    __nv_bfloat162 l2 = __floats2bfloat162_rn(r0, r1);
    const uint32_t hh = reinterpret_cast<uint32_t&>(h2);
    const uint32_t ll = reinterpret_cast<uint32_t&>(l2);
    const int rb = row >> 7, rl = row & 127;
#pragma unroll
    for (int seg = 0; seg < 3; ++seg) {
        const int kcol = seg * 2048 + col;
        const int ks = kcol >> 6, cl = kcol & 63;
        uint32_t off = (uint32_t)rl * 128 + ((cl >> 3) << 4);
        off ^= (off >> 3) & 0x70;
        const size_t a = ((size_t)(rb * NSTAGE_ITERS + ks) << 14) + off + ((cl & 7) << 1);
        const uint32_t val = isR ? (seg == 1 ? ll : hh) : (seg == 2 ? ll : hh);
        *(uint32_t*)(base + a) = val;
    }
}

__device__ __forceinline__ void pk_store_one(unsigned char* __restrict__ base,
                                             int row, int col, float v, bool isR)
{
    __nv_bfloat16 h = __float2bfloat16(v);
    __nv_bfloat16 l = __float2bfloat16(v - __bfloat162float(h));
    const int rb = row >> 7, rl = row & 127;
#pragma unroll
    for (int seg = 0; seg < 3; ++seg) {
        const int kcol = seg * 2048 + col;
        const int ks = kcol >> 6, cl = kcol & 63;
        uint32_t off = (uint32_t)rl * 128 + ((cl >> 3) << 4);
        off ^= (off >> 3) & 0x70;
        const size_t a = ((size_t)(rb * NSTAGE_ITERS + ks) << 14) + off + ((cl & 7) << 1);
        __nv_bfloat16 val = isR ? (seg == 1 ? l : h) : (seg == 2 ? l : h);
        *(__nv_bfloat16*)(base + a) = val;
    }
}

// ---------------------------------------------------------------------------
// Half-GEMM over upper-triangle tiles (grid = 136 CTAs, single wave).
// acc = Ap @ Bp^T (bf16x3 packed, fp32 acc). MODE-specific epilogue:
//  MODE 1 (Y  = X@X,  sym):  D=acc; PL,PR of acc; mirror to (c,r).
//  MODE 2 (Y2 = Y@Y,  sym):  D=acc; PR of acc; mirror.
//  MODE 3 (Y3 = Y@Y2, sym):  D=acc; PR of q = I + e1/6 + e2/120 + acc/5040; mirror.
//  MODE 4 (out = X@Q + P, P = I + e1/2 + e2/24 + e3/720):
//          D(r,c) = acc + P;  D(c,r) = P - acc  (acc antisym, P sym).
// ---------------------------------------------------------------------------
template <int MODE>
__global__ void __launch_bounds__(288, 1)
gemm_half(const unsigned char* __restrict__ Ap, const unsigned char* __restrict__ Bp,
          const float* __restrict__ e1, const float* __restrict__ e2,
          const float* __restrict__ e3,
          float* __restrict__ D,
          unsigned char* __restrict__ PL, unsigned char* __restrict__ PR)
{
    extern __shared__ __align__(1024) unsigned char smem[];
    const uint32_t sb = smem_u32(smem);
    const int tid = threadIdx.x;
    const int wid = tid >> 5;
    const int lid = tid & 31;

    // decode upper-triangle tile (mt <= nt)
    int bb = blockIdx.x, mt = 0;
    while (bb >= NTILE - mt) { bb -= NTILE - mt; ++mt; }
    const int nt = mt + bb;

    if (tid == 0) {
        for (int s = 0; s < STAGES; s++) {
            MBAR_INIT(sb + OFF_FULL  + s * 8, 1);
            MBAR_INIT(sb + OFF_EMPTY + s * 8, 8);
        }
    }
    __syncthreads();

    if (wid == 8) {
        if (lid == 0) {
            const unsigned char* srcA = Ap + (size_t)mt * NSTAGE_ITERS * A_STG_BYTES;
            const unsigned char* srcB = Bp + (size_t)nt * NSTAGE_ITERS * B_STG_BYTES;
            int st = 0, ph = 1;
            for (int ks = 0; ks < NSTAGE_ITERS; ++ks) {
                MBAR_WAIT(sb + OFF_EMPTY + st * 8, ph);
                MBAR_EXPECT_TX(sb + OFF_FULL + st * 8, A_STG_BYTES + B_STG_BYTES);
                bulk_g2s(sb + OFF_A + st * A_STG_BYTES, srcA + (size_t)ks * A_STG_BYTES,
                         A_STG_BYTES, sb + OFF_FULL + st * 8);
                bulk_g2s(sb + OFF_B + st * B_STG_BYTES, srcB + (size_t)ks * B_STG_BYTES,
                         B_STG_BYTES, sb + OFF_FULL + st * 8);
                if (++st == STAGES) { st = 0; ph ^= 1; }
            }
        }
        return;
    }

    const int mb = (wid >> 1) * 32;
    const int nb = (wid & 1) * 64;

    const int rA   = mb + (lid & 15);
    const int chA  = (lid >> 4);
    const uint32_t xorA = (rA & 7) << 4;
    const int rB   = nb + (lid & 7) + ((lid >> 4) << 3);
    const int chB  = (lid >> 3) & 1;
    const uint32_t xorB = (rB & 7) << 4;

    float acc[2][8][4];
#pragma unroll
    for (int mi = 0; mi < 2; mi++)
#pragma unroll
        for (int j = 0; j < 8; j++)
#pragma unroll
            for (int q = 0; q < 4; q++) acc[mi][j][q] = 0.0f;

    int st = 0, ph = 0;
#pragma unroll 1
    for (int ks = 0; ks < NSTAGE_ITERS; ++ks) {
        MBAR_WAIT(sb + OFF_FULL + st * 8, ph);
        const uint32_t baseA = sb + OFF_A + st * A_STG_BYTES + (uint32_t)rA * 128;
        const uint32_t baseB = sb + OFF_B + st * B_STG_BYTES + (uint32_t)rB * 128;

#pragma unroll
        for (int kk = 0; kk < 4; ++kk) {
            uint32_t a[2][4];
            const uint32_t kcA = (uint32_t)(kk * 2 + chA) * 16 ^ xorA;
            ldsm_x4(a[0], baseA + kcA);
            ldsm_x4(a[1], baseA + 2048 + kcA);

            uint32_t b[4][4];
            const uint32_t kcB = (uint32_t)(kk * 2 + chB) * 16 ^ xorB;
#pragma unroll
            for (int jj = 0; jj < 4; ++jj)
                ldsm_x4(b[jj], baseB + (uint32_t)jj * 2048 + kcB);

#pragma unroll
            for (int mi = 0; mi < 2; ++mi)
#pragma unroll
                for (int j = 0; j < 8; ++j)
                    mma_bf16(acc[mi][j], a[mi], &b[j >> 1][(j & 1) * 2]);
        }

        if (lid == 0) MBAR_ARRIVE(sb + OFF_EMPTY + st * 8);
        if (++st == STAGES) { st = 0; ph ^= 1; }
    }

    // ---- epilogue ----
    const int g = lid >> 2, t = lid & 3;
    const int rowBase = mt * TILE_M + mb;
    const int colBase = nt * TILE_N + nb;
    const bool offd = (mt != nt);

#pragma unroll
    for (int mi = 0; mi < 2; ++mi) {
#pragma unroll
        for (int half = 0; half < 2; ++half) {
            const int r0 = rowBase + mi * 16 + half * 8 + g;
#pragma unroll
            for (int j = 0; j < 8; ++j) {
                const int c = colBase + j * 8 + t * 2;
                const size_t e = (size_t)r0 * MATN + c;
                const float v0 = acc[mi][j][half * 2 + 0];
                const float v1 = acc[mi][j][half * 2 + 1];

                if (MODE <= 3) {
                    *(float2*)(D + e) = make_float2(v0, v1);
                }
                if (MODE == 1) {
                    pk_store_pair(PL, r0, c, v0, v1, false);
                    pk_store_pair(PR, r0, c, v0, v1, true);
                    if (offd) {
                        pk_store_one(PL, c,     r0, v0, false);
                        pk_store_one(PL, c + 1, r0, v1, false);
                        pk_store_one(PR, c,     r0, v0, true);
                        pk_store_one(PR, c + 1, r0, v1, true);
                    }
                }
                if (MODE == 2) {
                    pk_store_pair(PR, r0, c, v0, v1, true);
                    if (offd) {
                        pk_store_one(PR, c,     r0, v0, true);
                        pk_store_one(PR, c + 1, r0, v1, true);
                    }
                }
                if (MODE == 3) {
                    const float2 a1 = *(const float2*)(e1 + e);
                    const float2 a2 = *(const float2*)(e2 + e);
                    float q0 = (1.0f/6.0f) * a1.x + (1.0f/120.0f) * a2.x + (1.0f/5040.0f) * v0;
                    float q1 = (1.0f/6.0f) * a1.y + (1.0f/120.0f) * a2.y + (1.0f/5040.0f) * v1;
                    if (r0 == c)     q0 += 1.0f;
                    if (r0 == c + 1) q1 += 1.0f;
                    pk_store_pair(PR, r0, c, q0, q1, true);
                    if (offd) {
                        pk_store_one(PR, c,     r0, q0, true);
                        pk_store_one(PR, c + 1, r0, q1, true);
                    }
                }
                if (MODE == 4) {
                    const float2 a1 = *(const float2*)(e1 + e);
                    const float2 a2 = *(const float2*)(e2 + e);
                    const float2 a3 = *(const float2*)(e3 + e);
                    float P0 = 0.5f * a1.x + (1.0f/24.0f) * a2.x + (1.0f/720.0f) * a3.x;
                    float P1 = 0.5f * a1.y + (1.0f/24.0f) * a2.y + (1.0f/720.0f) * a3.y;
                    if (r0 == c)     P0 += 1.0f;
                    if (r0 == c + 1) P1 += 1.0f;
                    *(float2*)(D + e) = make_float2(P0 + v0, P1 + v1);
                    if (offd) {
                        D[(size_t)c       * MATN + r0] = P0 - v0;
                        D[(size_t)(c + 1) * MATN + r0] = P1 - v1;
                    }
                }
            }
        }
    }
}

// ---------------------------------------------------------------------------
// skew_pack: X = A - A^T packed only: PL_X (rows of X), PR_X (rows of -X,
// since X^T = -X). No fp32 X needed anywhere.
// ---------------------------------------------------------------------------
__global__ void skew_pack(const float* __restrict__ A,
                          unsigned char* __restrict__ PL, unsigned char* __restrict__ PR)
{
    __shared__ float tT[32][33];
    const int rblk = blockIdx.y * 32, cblk = blockIdx.x * 32;
    const int tfl = threadIdx.y * 16 + threadIdx.x;
#pragma unroll
    for (int e = tfl; e < 1024; e += 512) {
        const int u = e >> 5, v = e & 31;
        tT[u][v] = A[(size_t)(cblk + u) * MATN + rblk + v];
    }
    __syncthreads();
    const int r = rblk + threadIdx.y;
    const int c0 = cblk + threadIdx.x * 2;
    float2 av = *(const float2*)(A + (size_t)r * MATN + c0);
    const float x0 = av.x - tT[threadIdx.x * 2][threadIdx.y];
    const float x1 = av.y - tT[threadIdx.x * 2 + 1][threadIdx.y];
    pk_store_pair(PL, r, c0, x0, x1, false);
    pk_store_pair(PR, r, c0, -x0, -x1, true);
}

// ---------------------------------------------------------------------------
// expm(A - A^T) via even/odd split, degree 7 in X (cubic in Y = X^2):
//   Y = X^2; Y2 = Y^2; Y3 = Y*Y2
//   Q = I + Y/6 + Y2/120 + Y3/5040   (packed in GEMM3 epilogue)
//   P = I + Y/2 + Y2/24 + Y3/720     (combined in GEMM4 epilogue)
//   out = X*Q + P    (sym + antisym -> all 4 GEMMs on upper tiles only)
// ---------------------------------------------------------------------------
extern "C" void kernel_launch(void* const* d_in, const int* in_sizes, int n_in,
                              void* d_out, int out_size)
{
    const float* A = (const float*)d_in[0];
    float* out = (float*)d_out;

    float* fbase = nullptr;
    cudaGetSymbolAddress((void**)&fbase, g_f);
    float* Y  = fbase + 0 * (size_t)NN;
    float* Y2 = fbase + 1 * (size_t)NN;
    float* Y3 = fbase + 2 * (size_t)NN;

    unsigned char* pbase = nullptr;
    cudaGetSymbolAddress((void**)&pbase, g_pk);
    unsigned char* PL_X  = pbase + 0 * PK_BYTES;
    unsigned char* PR_X  = pbase + 1 * PK_BYTES;
    unsigned char* PL_Y  = pbase + 2 * PK_BYTES;
    unsigned char* PR_Y  = pbase + 3 * PK_BYTES;
    unsigned char* PR_Y2 = pbase + 4 * PK_BYTES;
    unsigned char* PR_Q  = pbase + 5 * PK_BYTES;

    cudaFuncSetAttribute(gemm_half<1>, cudaFuncAttributeMaxDynamicSharedMemorySize, SMEM_BYTES);
    cudaFuncSetAttribute(gemm_half<2>, cudaFuncAttributeMaxDynamicSharedMemorySize, SMEM_BYTES);
    cudaFuncSetAttribute(gemm_half<3>, cudaFuncAttributeMaxDynamicSharedMemorySize, SMEM_BYTES);
    cudaFuncSetAttribute(gemm_half<4>, cudaFuncAttributeMaxDynamicSharedMemorySize, SMEM_BYTES);

    const dim3 sGrid(MATN / 32, MATN / 32);
    const dim3 sBlk(16, 32);

    // packs of X
    skew_pack<<<sGrid, sBlk>>>(A, PL_X, PR_X);
    // Y = X @ X
    gemm_half<1><<<NBLK, 288, SMEM_BYTES>>>(PL_X, PR_X, nullptr, nullptr, nullptr,
                                            Y, PL_Y, PR_Y);
    // Y2 = Y @ Y
    gemm_half<2><<<NBLK, 288, SMEM_BYTES>>>(PL_Y, PR_Y, nullptr, nullptr, nullptr,
                                            Y2, nullptr, PR_Y2);
    // Y3 = Y @ Y2  (+ pack Q)
    gemm_half<3><<<NBLK, 288, SMEM_BYTES>>>(PL_Y, PR_Y2, Y, Y2, nullptr,
                                            Y3, nullptr, PR_Q);
    // out = X @ Q + P
    gemm_half<4><<<NBLK, 288, SMEM_BYTES>>>(PL_X, PR_Q, Y, Y2, Y3,
                                            out, nullptr, nullptr);
}

// round 13
// speedup vs baseline: 11.4217x; 1.2053x over previous
#include <cuda_runtime.h>
#include <cuda_bf16.h>
#include <cstdint>

#define MATN 2048
#define NN (MATN * MATN)
#define KP   6144                 // packed K = 3 * 2048 (bf16x3 split)
#define KC   64
#define NSTAGE_ITERS (KP / KC)    // 96
#define STAGES 4
#define TILE_M 128
#define TILE_N 128
#define NTILE (MATN / TILE_M)     // 16
#define NBLK  (NTILE * (NTILE + 1) / 2)   // 136 upper-triangle tiles

#define A_STG_BYTES (TILE_M * 128)
#define B_STG_BYTES (TILE_N * 128)

#define OFF_FULL   0
#define OFF_EMPTY  32
#define OFF_A      1024
#define OFF_B      (OFF_A + STAGES * A_STG_BYTES)
#define SMEM_BYTES (OFF_B + STAGES * B_STG_BYTES)      // 132096

#define PK_BYTES ((size_t)MATN * KP * 2)   // 25165824

// ---------------------------------------------------------------------------
// Scratch: 3 fp32 mats (Y, Y2, Y3) + 6 packed operand images
// ---------------------------------------------------------------------------
__device__ float g_f[3][NN];
__device__ __align__(128) unsigned char g_pk[6][PK_BYTES];

// ---------------------------------------------------------------------------
// PTX helpers (compute_103-safe)
// ---------------------------------------------------------------------------
__device__ __forceinline__ uint32_t smem_u32(const void* p) {
    uint32_t a;
    asm("{ .reg .u64 t; cvta.to.shared.u64 t, %1; cvt.u32.u64 %0, t; }" : "=r"(a) : "l"(p));
    return a;
}

#define MBAR_INIT(addr, cnt) \
    asm volatile("mbarrier.init.shared.b64 [%0], %1;" :: "r"(addr), "r"(cnt) : "memory")
#define MBAR_EXPECT_TX(addr, bytes) \
    asm volatile("mbarrier.arrive.expect_tx.shared.b64 _, [%0], %1;" :: "r"(addr), "r"(bytes) : "memory")
#define MBAR_ARRIVE(addr) \
    asm volatile("mbarrier.arrive.shared.b64 _, [%0];" :: "r"(addr) : "memory")

#define MBAR_WAIT(addr, ph) do {                                            \
    uint32_t _m = (addr), _p = (ph), _d;                                    \
    asm volatile("{\n\t.reg .pred p;\n\t"                                   \
        "mbarrier.try_wait.parity.acquire.cta.shared::cta.b64 p, [%1], %2;\n\t" \
        "selp.b32 %0, 1, 0, p;\n\t}"                                        \
        : "=r"(_d) : "r"(_m), "r"(_p) : "memory");                          \
    if (!_d) {                                                              \
        asm volatile("{\n\t.reg .pred P1;\n\t"                              \
            "WL_%=:\n\t"                                                    \
            "mbarrier.try_wait.parity.acquire.cta.shared::cta.b64 P1, [%0], %1, 0x989680;\n\t" \
            "@P1 bra.uni WD_%=;\n\t"                                        \
            "bra.uni WL_%=;\n\t"                                            \
            "WD_%=:\n\t}" :: "r"(_m), "r"(_p) : "memory");                  \
    }                                                                       \
} while (0)

__device__ __forceinline__ void bulk_g2s(uint32_t dst, const void* src, uint32_t bytes, uint32_t mbar) {
    asm volatile(
        "cp.async.bulk.shared::cluster.global.mbarrier::complete_tx::bytes [%0], [%1], %2, [%3];"
        :: "r"(dst), "l"(src), "r"(bytes), "r"(mbar) : "memory");
}

__device__ __forceinline__ void ldsm_x4(uint32_t* r, uint32_t addr) {
    asm volatile("ldmatrix.sync.aligned.m8n8.x4.shared.b16 {%0,%1,%2,%3}, [%4];"
                 : "=r"(r[0]), "=r"(r[1]), "=r"(r[2]), "=r"(r[3]) : "r"(addr));
}

__device__ __forceinline__ void mma_bf16(float* c, const uint32_t* a, const uint32_t* b) {
    asm volatile(
        "mma.sync.aligned.m16n8k16.row.col.f32.bf16.bf16.f32 "
        "{%0,%1,%2,%3}, {%4,%5,%6,%7}, {%8,%9}, {%0,%1,%2,%3};"
        : "+f"(c[0]), "+f"(c[1]), "+f"(c[2]), "+f"(c[3])
        : "r"(a[0]), "r"(a[1]), "r"(a[2]), "r"(a[3]), "r"(b[0]), "r"(b[1]));
}

// ---------------------------------------------------------------------------
// Packed-image stores (bf16x3 split). Left segs [h|h|l]; right segs [h;l;h].
// Truncating the K-stage loop yields exact sub-schemes:
//   96 stages: AhBh + AhBl + AlBh ; 64: Ah@B ; 32: Ah@Bh.
// ---------------------------------------------------------------------------
__device__ __forceinline__ void pk_store_pair(unsigned char* __restrict__ base,
                                              int row, int col, float v0, float v1, bool isR)
{
    __nv_bfloat162 h2 = __floats2bfloat162_rn(v0, v1);
    float r0 = v0 - __bfloat162float(__low2bfloat16(h2));
    float r1 = v1 - __bfloat162float(__high2bfloat16(h2));
    __nv_bfloat162 l2 = __floats2bfloat162_rn(r0, r1);
    const uint32_t hh = reinterpret_cast<uint32_t&>(h2);
    const uint32_t ll = reinterpret_cast<uint32_t&>(l2);
    const int rb = row >> 7, rl = row & 127;
#pragma unroll
    for (int seg = 0; seg < 3; ++seg) {
        const int kcol = seg * 2048 + col;
        const int ks = kcol >> 6, cl = kcol & 63;
        uint32_t off = (uint32_t)rl * 128 + ((cl >> 3) << 4);
        off ^= (off >> 3) & 0x70;
        const size_t a = ((size_t)(rb * NSTAGE_ITERS + ks) << 14) + off + ((cl & 7) << 1);
        const uint32_t val = isR ? (seg == 1 ? ll : hh) : (seg == 2 ? ll : hh);
        *(uint32_t*)(base + a) = val;
    }
}

__device__ __forceinline__ void pk_store_one(unsigned char* __restrict__ base,
                                             int row, int col, float v, bool isR)
{
    __nv_bfloat16 h = __float2bfloat16(v);
    __nv_bfloat16 l = __float2bfloat16(v - __bfloat162float(h));
    const int rb = row >> 7, rl = row & 127;
#pragma unroll
    for (int seg = 0; seg < 3; ++seg) {
        const int kcol = seg * 2048 + col;
        const int ks = kcol >> 6, cl = kcol & 63;
        uint32_t off = (uint32_t)rl * 128 + ((cl >> 3) << 4);
        off ^= (off >> 3) & 0x70;
        const size_t a = ((size_t)(rb * NSTAGE_ITERS + ks) << 14) + off + ((cl & 7) << 1);
        __nv_bfloat16 val = isR ? (seg == 1 ? l : h) : (seg == 2 ? l : h);
        *(__nv_bfloat16*)(base + a) = val;
    }
}

// ---------------------------------------------------------------------------
// Half-GEMM over upper-triangle tiles (grid = 136 CTAs, single wave).
// acc = Ap @ Bp^T over `nstages` K-stages. MODE-specific epilogue:
//  MODE 1 (Y  = X@X,  sym):  D=acc; PL,PR of acc; mirror to (c,r).
//  MODE 2 (Y2 = Y@Y,  sym):  D=acc; PR of acc; mirror.
//  MODE 3 (Y3 = Y@Y2, sym):  D=acc; PR of q = I + e1/6 + e2/120 + acc/5040; mirror.
//  MODE 4 (out = X@Q + P, P = I + e1/2 + e2/24 + e3/720):
//          D(r,c) = acc + P;  D(c,r) = P - acc  (acc antisym, P sym).
// ---------------------------------------------------------------------------
template <int MODE>
__global__ void __launch_bounds__(288, 1)
gemm_half(const unsigned char* __restrict__ Ap, const unsigned char* __restrict__ Bp,
          const float* __restrict__ e1, const float* __restrict__ e2,
          const float* __restrict__ e3,
          float* __restrict__ D,
          unsigned char* __restrict__ PL, unsigned char* __restrict__ PR,
          int nstages)
{
    extern __shared__ __align__(1024) unsigned char smem[];
    const uint32_t sb = smem_u32(smem);
    const int tid = threadIdx.x;
    const int wid = tid >> 5;
    const int lid = tid & 31;

    // decode upper-triangle tile (mt <= nt)
    int bb = blockIdx.x, mt = 0;
    while (bb >= NTILE - mt) { bb -= NTILE - mt; ++mt; }
    const int nt = mt + bb;

    if (tid == 0) {
        for (int s = 0; s < STAGES; s++) {
            MBAR_INIT(sb + OFF_FULL  + s * 8, 1);
            MBAR_INIT(sb + OFF_EMPTY + s * 8, 8);
        }
    }
    __syncthreads();

    if (wid == 8) {
        if (lid == 0) {
            const unsigned char* srcA = Ap + (size_t)mt * NSTAGE_ITERS * A_STG_BYTES;
            const unsigned char* srcB = Bp + (size_t)nt * NSTAGE_ITERS * B_STG_BYTES;
            int st = 0, ph = 1;
            for (int ks = 0; ks < nstages; ++ks) {
                MBAR_WAIT(sb + OFF_EMPTY + st * 8, ph);
                MBAR_EXPECT_TX(sb + OFF_FULL + st * 8, A_STG_BYTES + B_STG_BYTES);
                bulk_g2s(sb + OFF_A + st * A_STG_BYTES, srcA + (size_t)ks * A_STG_BYTES,
                         A_STG_BYTES, sb + OFF_FULL + st * 8);
                bulk_g2s(sb + OFF_B + st * B_STG_BYTES, srcB + (size_t)ks * B_STG_BYTES,
                         B_STG_BYTES, sb + OFF_FULL + st * 8);
                if (++st == STAGES) { st = 0; ph ^= 1; }
            }
        }
        return;
    }

    const int mb = (wid >> 1) * 32;
    const int nb = (wid & 1) * 64;

    const int rA   = mb + (lid & 15);
    const int chA  = (lid >> 4);
    const uint32_t xorA = (rA & 7) << 4;
    const int rB   = nb + (lid & 7) + ((lid >> 4) << 3);
    const int chB  = (lid >> 3) & 1;
    const uint32_t xorB = (rB & 7) << 4;

    float acc[2][8][4];
#pragma unroll
    for (int mi = 0; mi < 2; mi++)
#pragma unroll
        for (int j = 0; j < 8; j++)
#pragma unroll
            for (int q = 0; q < 4; q++) acc[mi][j][q] = 0.0f;

    int st = 0, ph = 0;
#pragma unroll 1
    for (int ks = 0; ks < nstages; ++ks) {
        MBAR_WAIT(sb + OFF_FULL + st * 8, ph);
        const uint32_t baseA = sb + OFF_A + st * A_STG_BYTES + (uint32_t)rA * 128;
        const uint32_t baseB = sb + OFF_B + st * B_STG_BYTES + (uint32_t)rB * 128;

#pragma unroll
        for (int kk = 0; kk < 4; ++kk) {
            uint32_t a[2][4];
            const uint32_t kcA = (uint32_t)(kk * 2 + chA) * 16 ^ xorA;
            ldsm_x4(a[0], baseA + kcA);
            ldsm_x4(a[1], baseA + 2048 + kcA);

            uint32_t b[4][4];
            const uint32_t kcB = (uint32_t)(kk * 2 + chB) * 16 ^ xorB;
#pragma unroll
            for (int jj = 0; jj < 4; ++jj)
                ldsm_x4(b[jj], baseB + (uint32_t)jj * 2048 + kcB);

#pragma unroll
            for (int mi = 0; mi < 2; ++mi)
#pragma unroll
                for (int j = 0; j < 8; ++j)
                    mma_bf16(acc[mi][j], a[mi], &b[j >> 1][(j & 1) * 2]);
        }

        if (lid == 0) MBAR_ARRIVE(sb + OFF_EMPTY + st * 8);
        if (++st == STAGES) { st = 0; ph ^= 1; }
    }

    // ---- epilogue ----
    const int g = lid >> 2, t = lid & 3;
    const int rowBase = mt * TILE_M + mb;
    const int colBase = nt * TILE_N + nb;
    const bool offd = (mt != nt);

#pragma unroll
    for (int mi = 0; mi < 2; ++mi) {
#pragma unroll
        for (int half = 0; half < 2; ++half) {
            const int r0 = rowBase + mi * 16 + half * 8 + g;
#pragma unroll
            for (int j = 0; j < 8; ++j) {
                const int c = colBase + j * 8 + t * 2;
                const size_t e = (size_t)r0 * MATN + c;
                const float v0 = acc[mi][j][half * 2 + 0];
                const float v1 = acc[mi][j][half * 2 + 1];

                if (MODE <= 3) {
                    *(float2*)(D + e) = make_float2(v0, v1);
                }
                if (MODE == 1) {
                    pk_store_pair(PL, r0, c, v0, v1, false);
                    pk_store_pair(PR, r0, c, v0, v1, true);
                    if (offd) {
                        pk_store_one(PL, c,     r0, v0, false);
                        pk_store_one(PL, c + 1, r0, v1, false);
                        pk_store_one(PR, c,     r0, v0, true);
                        pk_store_one(PR, c + 1, r0, v1, true);
                    }
                }
                if (MODE == 2) {
                    pk_store_pair(PR, r0, c, v0, v1, true);
                    if (offd) {
                        pk_store_one(PR, c,     r0, v0, true);
                        pk_store_one(PR, c + 1, r0, v1, true);
                    }
                }
                if (MODE == 3) {
                    const float2 a1 = *(const float2*)(e1 + e);
                    const float2 a2 = *(const float2*)(e2 + e);
                    float q0 = (1.0f/6.0f) * a1.x + (1.0f/120.0f) * a2.x + (1.0f/5040.0f) * v0;
                    float q1 = (1.0f/6.0f) * a1.y + (1.0f/120.0f) * a2.y + (1.0f/5040.0f) * v1;
                    if (r0 == c)     q0 += 1.0f;
                    if (r0 == c + 1) q1 += 1.0f;
                    pk_store_pair(PR, r0, c, q0, q1, true);
                    if (offd) {
                        pk_store_one(PR, c,     r0, q0, true);
                        pk_store_one(PR, c + 1, r0, q1, true);
                    }
                }
                if (MODE == 4) {
                    const float2 a1 = *(const float2*)(e1 + e);
                    const float2 a2 = *(const float2*)(e2 + e);
                    const float2 a3 = *(const float2*)(e3 + e);
                    float P0 = 0.5f * a1.x + (1.0f/24.0f) * a2.x + (1.0f/720.0f) * a3.x;
                    float P1 = 0.5f * a1.y + (1.0f/24.0f) * a2.y + (1.0f/720.0f) * a3.y;
                    if (r0 == c)     P0 += 1.0f;
                    if (r0 == c + 1) P1 += 1.0f;
                    *(float2*)(D + e) = make_float2(P0 + v0, P1 + v1);
                    if (offd) {
                        D[(size_t)c       * MATN + r0] = P0 - v0;
                        D[(size_t)(c + 1) * MATN + r0] = P1 - v1;
                    }
                }
            }
        }
    }
}

// ---------------------------------------------------------------------------
// skew_pack: X = A - A^T packed only: PL_X (rows of X), PR_X (rows of -X,
// since X^T = -X). No fp32 X needed anywhere.
// ---------------------------------------------------------------------------
__global__ void skew_pack(const float* __restrict__ A,
                          unsigned char* __restrict__ PL, unsigned char* __restrict__ PR)
{
    __shared__ float tT[32][33];
    const int rblk = blockIdx.y * 32, cblk = blockIdx.x * 32;
    const int tfl = threadIdx.y * 16 + threadIdx.x;
#pragma unroll
    for (int e = tfl; e < 1024; e += 512) {
        const int u = e >> 5, v = e & 31;
        tT[u][v] = A[(size_t)(cblk + u) * MATN + rblk + v];
    }
    __syncthreads();
    const int r = rblk + threadIdx.y;
    const int c0 = cblk + threadIdx.x * 2;
    float2 av = *(const float2*)(A + (size_t)r * MATN + c0);
    const float x0 = av.x - tT[threadIdx.x * 2][threadIdx.y];
    const float x1 = av.y - tT[threadIdx.x * 2 + 1][threadIdx.y];
    pk_store_pair(PL, r, c0, x0, x1, false);
    pk_store_pair(PR, r, c0, -x0, -x1, true);
}

// ---------------------------------------------------------------------------
// expm(A - A^T) via even/odd split, degree 7 in X (cubic in Y = X^2):
//   Y = X^2 (full split, 96 stg); Y2 = Y^2 (64 stg); Y3 = Y*Y2 (32 stg)
//   Q = I + Y/6 + Y2/120 + Y3/5040   (packed in GEMM3 epilogue)
//   P = I + Y/2 + Y2/24 + Y3/720     (combined in GEMM4 epilogue)
//   out = X*Q + P  (full split, 96 stg); all GEMMs on upper tiles only.
// ---------------------------------------------------------------------------
extern "C" void kernel_launch(void* const* d_in, const int* in_sizes, int n_in,
                              void* d_out, int out_size)
{
    const float* A = (const float*)d_in[0];
    float* out = (float*)d_out;

    float* fbase = nullptr;
    cudaGetSymbolAddress((void**)&fbase, g_f);
    float* Y  = fbase + 0 * (size_t)NN;
    float* Y2 = fbase + 1 * (size_t)NN;
    float* Y3 = fbase + 2 * (size_t)NN;

    unsigned char* pbase = nullptr;
    cudaGetSymbolAddress((void**)&pbase, g_pk);
    unsigned char* PL_X  = pbase + 0 * PK_BYTES;
    unsigned char* PR_X  = pbase + 1 * PK_BYTES;
    unsigned char* PL_Y  = pbase + 2 * PK_BYTES;
    unsigned char* PR_Y  = pbase + 3 * PK_BYTES;
    unsigned char* PR_Y2 = pbase + 4 * PK_BYTES;
    unsigned char* PR_Q  = pbase + 5 * PK_BYTES;

    cudaFuncSetAttribute(gemm_half<1>, cudaFuncAttributeMaxDynamicSharedMemorySize, SMEM_BYTES);
    cudaFuncSetAttribute(gemm_half<2>, cudaFuncAttributeMaxDynamicSharedMemorySize, SMEM_BYTES);
    cudaFuncSetAttribute(gemm_half<3>, cudaFuncAttributeMaxDynamicSharedMemorySize, SMEM_BYTES);
    cudaFuncSetAttribute(gemm_half<4>, cudaFuncAttributeMaxDynamicSharedMemorySize, SMEM_BYTES);

    const dim3 sGrid(MATN / 32, MATN / 32);
    const dim3 sBlk(16, 32);

    // packs of X
    skew_pack<<<sGrid, sBlk>>>(A, PL_X, PR_X);
    // Y = X @ X            (full precision: 96 stages)
    gemm_half<1><<<NBLK, 288, SMEM_BYTES>>>(PL_X, PR_X, nullptr, nullptr, nullptr,
                                            Y, PL_Y, PR_Y, 96);
    // Y2 = Y @ Y           (Yh @ Y: 64 stages — error enters /~20)
    gemm_half<2><<<NBLK, 288, SMEM_BYTES>>>(PL_Y, PR_Y, nullptr, nullptr, nullptr,
                                            Y2, nullptr, PR_Y2, 64);
    // Y3 = Y @ Y2 (+ pack Q)  (Yh @ Y2h: 32 stages — error enters /~500)
    gemm_half<3><<<NBLK, 288, SMEM_BYTES>>>(PL_Y, PR_Y2, Y, Y2, nullptr,
                                            Y3, nullptr, PR_Q, 32);
    // out = X @ Q + P      (full precision: 96 stages)
    gemm_half<4><<<NBLK, 288, SMEM_BYTES>>>(PL_X, PR_Q, Y, Y2, Y3,
                                            out, nullptr, nullptr, 96);
}

// round 14
// speedup vs baseline: 13.3391x; 1.1679x over previous
#include <cuda_runtime.h>
#include <cuda_bf16.h>
#include <cstdint>

#define MATN 2048
#define NN (MATN * MATN)
#define KP   6144                 // packed K = 3 * 2048 (bf16x3 split)
#define KC   64
#define NSTAGE_ITERS (KP / KC)    // 96
#define STAGES 4
#define TILE_M 128
#define TILE_N 128
#define NTILE (MATN / TILE_M)     // 16
#define NBLK  (NTILE * (NTILE + 1) / 2)   // 136 upper-triangle tiles

#define A_STG_BYTES (TILE_M * 128)
#define B_STG_BYTES (TILE_N * 128)

#define OFF_FULL   0
#define OFF_EMPTY  32
#define OFF_A      1024
#define OFF_B      (OFF_A + STAGES * A_STG_BYTES)
#define SMEM_BYTES (OFF_B + STAGES * B_STG_BYTES)      // 132096
// epilogue staging reuses [OFF_A, OFF_A + 128*132*4) = 68608 bytes < SMEM_BYTES

#define PK_BYTES ((size_t)MATN * KP * 2)   // 25165824

// ---------------------------------------------------------------------------
// Scratch: 3 fp32 mats (Y, Y2, P) + 6 packed operand images
// ---------------------------------------------------------------------------
__device__ float g_f[3][NN];
__device__ __align__(128) unsigned char g_pk[6][PK_BYTES];

// ---------------------------------------------------------------------------
// PTX helpers (compute_103-safe)
// ---------------------------------------------------------------------------
__device__ __forceinline__ uint32_t smem_u32(const void* p) {
    uint32_t a;
    asm("{ .reg .u64 t; cvta.to.shared.u64 t, %1; cvt.u32.u64 %0, t; }" : "=r"(a) : "l"(p));
    return a;
}

#define MBAR_INIT(addr, cnt) \
    asm volatile("mbarrier.init.shared.b64 [%0], %1;" :: "r"(addr), "r"(cnt) : "memory")
#define MBAR_EXPECT_TX(addr, bytes) \
    asm volatile("mbarrier.arrive.expect_tx.shared.b64 _, [%0], %1;" :: "r"(addr), "r"(bytes) : "memory")
#define MBAR_ARRIVE(addr) \
    asm volatile("mbarrier.arrive.shared.b64 _, [%0];" :: "r"(addr) : "memory")

#define MBAR_WAIT(addr, ph) do {                                            \
    uint32_t _m = (addr), _p = (ph), _d;                                    \
    asm volatile("{\n\t.reg .pred p;\n\t"                                   \
        "mbarrier.try_wait.parity.acquire.cta.shared::cta.b64 p, [%1], %2;\n\t" \
        "selp.b32 %0, 1, 0, p;\n\t}"                                        \
        : "=r"(_d) : "r"(_m), "r"(_p) : "memory");                          \
    if (!_d) {                                                              \
        asm volatile("{\n\t.reg .pred P1;\n\t"                              \
            "WL_%=:\n\t"                                                    \
            "mbarrier.try_wait.parity.acquire.cta.shared::cta.b64 P1, [%0], %1, 0x989680;\n\t" \
            "@P1 bra.uni WD_%=;\n\t"                                        \
            "bra.uni WL_%=;\n\t"                                            \
            "WD_%=:\n\t}" :: "r"(_m), "r"(_p) : "memory");                  \
    }                                                                       \
} while (0)

__device__ __forceinline__ void bulk_g2s(uint32_t dst, const void* src, uint32_t bytes, uint32_t mbar) {
    asm volatile(
        "cp.async.bulk.shared::cluster.global.mbarrier::complete_tx::bytes [%0], [%1], %2, [%3];"
        :: "r"(dst), "l"(src), "r"(bytes), "r"(mbar) : "memory");
}

__device__ __forceinline__ void ldsm_x4(uint32_t* r, uint32_t addr) {
    asm volatile("ldmatrix.sync.aligned.m8n8.x4.shared.b16 {%0,%1,%2,%3}, [%4];"
                 : "=r"(r[0]), "=r"(r[1]), "=r"(r[2]), "=r"(r[3]) : "r"(addr));
}

__device__ __forceinline__ void mma_bf16(float* c, const uint32_t* a, const uint32_t* b) {
    asm volatile(
        "mma.sync.aligned.m16n8k16.row.col.f32.bf16.bf16.f32 "
        "{%0,%1,%2,%3}, {%4,%5,%6,%7}, {%8,%9}, {%0,%1,%2,%3};"
        : "+f"(c[0]), "+f"(c[1]), "+f"(c[2]), "+f"(c[3])
        : "r"(a[0]), "r"(a[1]), "r"(a[2]), "r"(a[3]), "r"(b[0]), "r"(b[1]));
}

// ---------------------------------------------------------------------------
// Packed-image layout (bf16x3 split). Left segs [h|h|l]; right segs [h;l;h].
// Truncating K-stages gives exact sub-schemes: 96: hh+hl+lh ; 64: h@full ; 32: h@h.
// ---------------------------------------------------------------------------
__device__ __forceinline__ void split8(const float* v, uint4& H, uint4& L) {
    uint32_t h[4], l[4];
#pragma unroll
    for (int i = 0; i < 4; ++i) {
        __nv_bfloat162 h2 = __floats2bfloat162_rn(v[2*i], v[2*i+1]);
        float r0 = v[2*i]   - __bfloat162float(__low2bfloat16(h2));
        float r1 = v[2*i+1] - __bfloat162float(__high2bfloat16(h2));
        __nv_bfloat162 l2 = __floats2bfloat162_rn(r0, r1);
        h[i] = reinterpret_cast<uint32_t&>(h2);
        l[i] = reinterpret_cast<uint32_t&>(l2);
    }
    H = make_uint4(h[0], h[1], h[2], h[3]);
    L = make_uint4(l[0], l[1], l[2], l[3]);
}

// 8 consecutive k-cols (col8 % 8 == 0) = one 16B swizzle chunk per segment.
__device__ __forceinline__ void pk_chunk(unsigned char* __restrict__ base, int row, int col8,
                                         const uint4& H, const uint4& L, bool isR) {
    const int rb = row >> 7, rl = row & 127;
#pragma unroll
    for (int seg = 0; seg < 3; ++seg) {
        const int kcol = seg * 2048 + col8;
        const int ks = kcol >> 6, cl = kcol & 63;
        uint32_t off = (uint32_t)rl * 128 + ((cl >> 3) << 4);
        off ^= (off >> 3) & 0x70;
        const size_t a = ((size_t)(rb * NSTAGE_ITERS + ks) << 14) + off;
        const bool useL = isR ? (seg == 1) : (seg == 2);
        *(uint4*)(base + a) = useL ? L : H;
    }
}

// scalar-pair store (used by skew_pack only)
__device__ __forceinline__ void pk_store_pair(unsigned char* __restrict__ base,
                                              int row, int col, float v0, float v1, bool isR)
{
    __nv_bfloat162 h2 = __floats2bfloat162_rn(v0, v1);
    float r0 = v0 - __bfloat162float(__low2bfloat16(h2));
    float r1 = v1 - __bfloat162float(__high2bfloat16(h2));
    __nv_bfloat162 l2 = __floats2bfloat162_rn(r0, r1);
    const uint32_t hh = reinterpret_cast<uint32_t&>(h2);
    const uint32_t ll = reinterpret_cast<uint32_t&>(l2);
    const int rb = row >> 7, rl = row & 127;
#pragma unroll
    for (int seg = 0; seg < 3; ++seg) {
        const int kcol = seg * 2048 + col;
        const int ks = kcol >> 6, cl = kcol & 63;
        uint32_t off = (uint32_t)rl * 128 + ((cl >> 3) << 4);
        off ^= (off >> 3) & 0x70;
        const size_t a = ((size_t)(rb * NSTAGE_ITERS + ks) << 14) + off + ((cl & 7) << 1);
        const uint32_t val = isR ? (seg == 1 ? ll : hh) : (seg == 2 ? ll : hh);
        *(uint32_t*)(base + a) = val;
    }
}

// ---------------------------------------------------------------------------
// Half-GEMM over upper-triangle tiles (136 CTAs, single wave).
// acc = Ap @ Bp^T over nstages. Chunked epilogue via smem staging:
//  MODE 1 (Y  = X@X,  sym):  D=full Y; PL,PR images (direct + mirror).
//  MODE 2 (Y2 = Y@Y,  sym):  D=full Y2; PR image.
//  MODE 3 (Y3 = Y@Y2, sym):  D=full P = I + e1/2 + e2/24 + acc/720;
//                            PR image of Q = I + e1/6 + e2/120 + acc/5040.
//  MODE 4 (out = X@Q + P):   D(r,c) = e1 + acc; D(c,r) = e1 - acc (P sym via e1).
// ---------------------------------------------------------------------------
template <int MODE>
__global__ void __launch_bounds__(288, 1)
gemm_half(const unsigned char* __restrict__ Ap, const unsigned char* __restrict__ Bp,
          const float* __restrict__ e1, const float* __restrict__ e2,
          float* __restrict__ D,
          unsigned char* __restrict__ PL, unsigned char* __restrict__ PR,
          int nstages)
{
    extern __shared__ __align__(1024) unsigned char smem[];
    const uint32_t sb = smem_u32(smem);
    const int tid = threadIdx.x;
    const int wid = tid >> 5;
    const int lid = tid & 31;
    const int g = lid >> 2, t = lid & 3;

    // decode upper-triangle tile (mt <= nt)
    int bb = blockIdx.x, mt = 0;
    while (bb >= NTILE - mt) { bb -= NTILE - mt; ++mt; }
    const int nt = mt + bb;

    const int mb = (wid >> 1) * 32;   // consumer warp row base (garbage for wid=8, unused)
    const int nb = (wid & 1) * 64;

    if (tid == 0) {
        for (int s = 0; s < STAGES; s++) {
            MBAR_INIT(sb + OFF_FULL  + s * 8, 1);
            MBAR_INIT(sb + OFF_EMPTY + s * 8, 8);
        }
    }
    __syncthreads();

    float acc[2][8][4];
#pragma unroll
    for (int mi = 0; mi < 2; mi++)
#pragma unroll
        for (int j = 0; j < 8; j++)
#pragma unroll
            for (int q = 0; q < 4; q++) acc[mi][j][q] = 0.0f;

    if (wid == 8) {
        // ---- producer ----
        if (lid == 0) {
            const unsigned char* srcA = Ap + (size_t)mt * NSTAGE_ITERS * A_STG_BYTES;
            const unsigned char* srcB = Bp + (size_t)nt * NSTAGE_ITERS * B_STG_BYTES;
            int st = 0, ph = 1;
            for (int ks = 0; ks < nstages; ++ks) {
                MBAR_WAIT(sb + OFF_EMPTY + st * 8, ph);
                MBAR_EXPECT_TX(sb + OFF_FULL + st * 8, A_STG_BYTES + B_STG_BYTES);
                bulk_g2s(sb + OFF_A + st * A_STG_BYTES, srcA + (size_t)ks * A_STG_BYTES,
                         A_STG_BYTES, sb + OFF_FULL + st * 8);
                bulk_g2s(sb + OFF_B + st * B_STG_BYTES, srcB + (size_t)ks * B_STG_BYTES,
                         B_STG_BYTES, sb + OFF_FULL + st * 8);
                if (++st == STAGES) { st = 0; ph ^= 1; }
            }
        }
    } else {
        // ---- consumers: warp tile 32(m) x 64(n) ----
        const int rA   = mb + (lid & 15);
        const int chA  = (lid >> 4);
        const uint32_t xorA = (rA & 7) << 4;
        const int rB   = nb + (lid & 7) + ((lid >> 4) << 3);
        const int chB  = (lid >> 3) & 1;
        const uint32_t xorB = (rB & 7) << 4;

        int st = 0, ph = 0;
#pragma unroll 1
        for (int ks = 0; ks < nstages; ++ks) {
            MBAR_WAIT(sb + OFF_FULL + st * 8, ph);
            const uint32_t baseA = sb + OFF_A + st * A_STG_BYTES + (uint32_t)rA * 128;
            const uint32_t baseB = sb + OFF_B + st * B_STG_BYTES + (uint32_t)rB * 128;

#pragma unroll
            for (int kk = 0; kk < 4; ++kk) {
                uint32_t a[2][4];
                const uint32_t kcA = (uint32_t)(kk * 2 + chA) * 16 ^ xorA;
                ldsm_x4(a[0], baseA + kcA);
                ldsm_x4(a[1], baseA + 2048 + kcA);

                uint32_t b[4][4];
                const uint32_t kcB = (uint32_t)(kk * 2 + chB) * 16 ^ xorB;
#pragma unroll
                for (int jj = 0; jj < 4; ++jj)
                    ldsm_x4(b[jj], baseB + (uint32_t)jj * 2048 + kcB);

#pragma unroll
                for (int mi = 0; mi < 2; ++mi)
#pragma unroll
                    for (int j = 0; j < 8; ++j)
                        mma_bf16(acc[mi][j], a[mi], &b[j >> 1][(j & 1) * 2]);
            }

            if (lid == 0) MBAR_ARRIVE(sb + OFF_EMPTY + st * 8);
            if (++st == STAGES) { st = 0; ph ^= 1; }
        }
    }

    // ---- stage acc tile to smem (fp32, stride 132) ----
    __syncthreads();
    float* stg = (float*)(smem + OFF_A);
    if (wid < 8) {
#pragma unroll
        for (int mi = 0; mi < 2; ++mi)
#pragma unroll
            for (int half = 0; half < 2; ++half) {
                const int rl = mb + mi * 16 + half * 8 + g;
#pragma unroll
                for (int j = 0; j < 8; ++j) {
                    const int cl = nb + j * 8 + t * 2;
                    stg[rl * 132 + cl]     = acc[mi][j][half * 2 + 0];
                    stg[rl * 132 + cl + 1] = acc[mi][j][half * 2 + 1];
                }
            }
    }
    __syncthreads();

    // ---- chunked epilogue: 8-element row chunks, all 288 threads ----
    const int rowBase = mt * TILE_M, colBase = nt * TILE_N;
    const bool offd = (mt != nt);

#pragma unroll 1
    for (int task = tid; task < 2048; task += 288) {
        const int rl  = task >> 4;
        const int ch8 = (task & 15) << 3;
        float v[8];
        *(float4*)&v[0] = *(const float4*)&stg[rl * 132 + ch8];
        *(float4*)&v[4] = *(const float4*)&stg[rl * 132 + ch8 + 4];
        const int gr  = rowBase + rl;
        const int gc8 = colBase + ch8;
        const size_t e = (size_t)gr * MATN + gc8;

        if (MODE == 1 || MODE == 2) {
            *(float4*)&D[e]     = *(float4*)&v[0];
            *(float4*)&D[e + 4] = *(float4*)&v[4];
            uint4 H, L; split8(v, H, L);
            if (MODE == 1) pk_chunk(PL, gr, gc8, H, L, false);
            pk_chunk(PR, gr, gc8, H, L, true);
        }
        if (MODE == 3) {
            float y[8], z[8], q[8], p[8];
            *(float4*)&y[0] = *(const float4*)&e1[e]; *(float4*)&y[4] = *(const float4*)&e1[e + 4];
            *(float4*)&z[0] = *(const float4*)&e2[e]; *(float4*)&z[4] = *(const float4*)&e2[e + 4];
#pragma unroll
            for (int i = 0; i < 8; ++i) {
                q[i] = y[i] * (1.0f/6.0f) + z[i] * (1.0f/120.0f) + v[i] * (1.0f/5040.0f);
                p[i] = y[i] * 0.5f        + z[i] * (1.0f/24.0f)  + v[i] * (1.0f/720.0f);
            }
            const int d = gr - gc8;
            if (d >= 0 && d < 8) { q[d] += 1.0f; p[d] += 1.0f; }
            *(float4*)&D[e]     = *(float4*)&p[0];
            *(float4*)&D[e + 4] = *(float4*)&p[4];
            uint4 H, L; split8(q, H, L);
            pk_chunk(PR, gr, gc8, H, L, true);
        }
        if (MODE == 4) {
            float p[8];
            *(float4*)&p[0] = *(const float4*)&e1[e]; *(float4*)&p[4] = *(const float4*)&e1[e + 4];
#pragma unroll
            for (int i = 0; i < 8; ++i) p[i] += v[i];
            *(float4*)&D[e]     = *(float4*)&p[0];
            *(float4*)&D[e + 4] = *(float4*)&p[4];
        }
    }

    if (offd) {
        // mirror: destination row gr = colBase + cc, cols gc8 = rowBase + chb8..
        // acc value at mirror = acc[chb8+k][cc] (sym; antisym for MODE 4 uses -v).
#pragma unroll 1
        for (int task = tid; task < 2048; task += 288) {
            const int cc   = task >> 4;
            const int chb8 = (task & 15) << 3;
            float v[8];
#pragma unroll
            for (int k = 0; k < 8; ++k) v[k] = stg[(chb8 + k) * 132 + cc];
            const int gr  = colBase + cc;
            const int gc8 = rowBase + chb8;
            const size_t e = (size_t)gr * MATN + gc8;

            if (MODE == 1 || MODE == 2) {
                *(float4*)&D[e]     = *(float4*)&v[0];
                *(float4*)&D[e + 4] = *(float4*)&v[4];
                uint4 H, L; split8(v, H, L);
                if (MODE == 1) pk_chunk(PL, gr, gc8, H, L, false);
                pk_chunk(PR, gr, gc8, H, L, true);
            }
            if (MODE == 3) {
                float y[8], z[8], q[8], p[8];
                *(float4*)&y[0] = *(const float4*)&e1[e]; *(float4*)&y[4] = *(const float4*)&e1[e + 4];
                *(float4*)&z[0] = *(const float4*)&e2[e]; *(float4*)&z[4] = *(const float4*)&e2[e + 4];
#pragma unroll
                for (int i = 0; i < 8; ++i) {
                    q[i] = y[i] * (1.0f/6.0f) + z[i] * (1.0f/120.0f) + v[i] * (1.0f/5040.0f);
                    p[i] = y[i] * 0.5f        + z[i] * (1.0f/24.0f)  + v[i] * (1.0f/720.0f);
                }
                *(float4*)&D[e]     = *(float4*)&p[0];
                *(float4*)&D[e + 4] = *(float4*)&p[4];
                uint4 H, L; split8(q, H, L);
                pk_chunk(PR, gr, gc8, H, L, true);
            }
            if (MODE == 4) {
                float p[8];
                *(float4*)&p[0] = *(const float4*)&e1[e]; *(float4*)&p[4] = *(const float4*)&e1[e + 4];
#pragma unroll
                for (int i = 0; i < 8; ++i) p[i] -= v[i];
                *(float4*)&D[e]     = *(float4*)&p[0];
                *(float4*)&D[e + 4] = *(float4*)&p[4];
            }
        }
    }
}

// ---------------------------------------------------------------------------
// skew_pack: X = A - A^T packed only: PL_X (rows of X), PR_X (rows of -X).
// ---------------------------------------------------------------------------
__global__ void skew_pack(const float* __restrict__ A,
                          unsigned char* __restrict__ PL, unsigned char* __restrict__ PR)
{
    __shared__ float tT[32][33];
    const int rblk = blockIdx.y * 32, cblk = blockIdx.x * 32;
    const int tfl = threadIdx.y * 16 + threadIdx.x;
#pragma unroll
    for (int e = tfl; e < 1024; e += 512) {
        const int u = e >> 5, v = e & 31;
        tT[u][v] = A[(size_t)(cblk + u) * MATN + rblk + v];
    }
    __syncthreads();
    const int r = rblk + threadIdx.y;
    const int c0 = cblk + threadIdx.x * 2;
    float2 av = *(const float2*)(A + (size_t)r * MATN + c0);
    const float x0 = av.x - tT[threadIdx.x * 2][threadIdx.y];
    const float x1 = av.y - tT[threadIdx.x * 2 + 1][threadIdx.y];
    pk_store_pair(PL, r, c0, x0, x1, false);
    pk_store_pair(PR, r, c0, -x0, -x1, true);
}

// ---------------------------------------------------------------------------
// expm(A - A^T) via even/odd split, degree 7 in X (cubic in Y = X^2):
//   Y = X^2 (96 stg); Y2 = Y^2 (32 stg); Y3 = Y*Y2 (32 stg, folds P & packs Q)
//   out = X*Q + P (96 stg). All GEMMs upper-triangle-only, mirrored epilogues.
// ---------------------------------------------------------------------------
extern "C" void kernel_launch(void* const* d_in, const int* in_sizes, int n_in,
                              void* d_out, int out_size)
{
    const float* A = (const float*)d_in[0];
    float* out = (float*)d_out;

    float* fbase = nullptr;
    cudaGetSymbolAddress((void**)&fbase, g_f);
    float* Y  = fbase + 0 * (size_t)NN;
    float* Y2 = fbase + 1 * (size_t)NN;
    float* P  = fbase + 2 * (size_t)NN;

    unsigned char* pbase = nullptr;
    cudaGetSymbolAddress((void**)&pbase, g_pk);
    unsigned char* PL_X  = pbase + 0 * PK_BYTES;
    unsigned char* PR_X  = pbase + 1 * PK_BYTES;
    unsigned char* PL_Y  = pbase + 2 * PK_BYTES;
    unsigned char* PR_Y  = pbase + 3 * PK_BYTES;
    unsigned char* PR_Y2 = pbase + 4 * PK_BYTES;
    unsigned char* PR_Q  = pbase + 5 * PK_BYTES;

    cudaFuncSetAttribute(gemm_half<1>, cudaFuncAttributeMaxDynamicSharedMemorySize, SMEM_BYTES);
    cudaFuncSetAttribute(gemm_half<2>, cudaFuncAttributeMaxDynamicSharedMemorySize, SMEM_BYTES);
    cudaFuncSetAttribute(gemm_half<3>, cudaFuncAttributeMaxDynamicSharedMemorySize, SMEM_BYTES);
    cudaFuncSetAttribute(gemm_half<4>, cudaFuncAttributeMaxDynamicSharedMemorySize, SMEM_BYTES);

    const dim3 sGrid(MATN / 32, MATN / 32);
    const dim3 sBlk(16, 32);

    // packs of X
    skew_pack<<<sGrid, sBlk>>>(A, PL_X, PR_X);
    // Y = X @ X                (full split: 96 stages)
    gemm_half<1><<<NBLK, 288, SMEM_BYTES>>>(PL_X, PR_X, nullptr, nullptr,
                                            Y, PL_Y, PR_Y, 96);
    // Y2 = Y @ Y               (Yh @ Yh: 32 stages — error weight ~1/24)
    gemm_half<2><<<NBLK, 288, SMEM_BYTES>>>(PL_Y, PR_Y, nullptr, nullptr,
                                            Y2, nullptr, PR_Y2, 32);
    // Y3 = Y @ Y2; epilogue: P = I + Y/2 + Y2/24 + Y3/720 (fp32, full),
    //                        Q = I + Y/6 + Y2/120 + Y3/5040 (packed PR)
    gemm_half<3><<<NBLK, 288, SMEM_BYTES>>>(PL_Y, PR_Y2, Y, Y2,
                                            P, nullptr, PR_Q, 32);
    // out = X @ Q + P          (full split: 96 stages)
    gemm_half<4><<<NBLK, 288, SMEM_BYTES>>>(PL_X, PR_Q, P, nullptr,
                                            out, nullptr, nullptr, 96);
}

// round 15
// speedup vs baseline: 14.9997x; 1.1245x over previous
#include <cuda_runtime.h>
#include <cuda_bf16.h>
#include <cstdint>

#define MATN 2048
#define NN (MATN * MATN)
#define KC   64
#define STAGES 4
#define TILE_M 128
#define TILE_N 128
#define NTILE (MATN / TILE_M)     // 16
#define NBLK  (NTILE * (NTILE + 1) / 2)   // 136 upper-triangle tiles
#define NSTG_STORED 64            // stored K-blocks per image row-block: [h:32 | l:32]

#define A_STG_BYTES (TILE_M * 128)
#define B_STG_BYTES (TILE_N * 128)

#define OFF_FULL   0
#define OFF_EMPTY  32
#define OFF_A      1024
#define OFF_B      (OFF_A + STAGES * A_STG_BYTES)
#define SMEM_BYTES (OFF_B + STAGES * B_STG_BYTES)      // 132096
// epilogue staging reuses [OFF_A, OFF_A + 128*132*4) = 67584 bytes < SMEM_BYTES

#define PK_BYTES ((size_t)MATN * 4096 * 2)   // 16 MB per dedup'd image

// ---------------------------------------------------------------------------
// Scratch: 3 fp32 mats (Y, Y2, P) + 6 dedup'd packed operand images
// ---------------------------------------------------------------------------
__device__ float g_f[3][NN];
__device__ __align__(128) unsigned char g_pk[6][PK_BYTES];

// ---------------------------------------------------------------------------
// PTX helpers (compute_103-safe)
// ---------------------------------------------------------------------------
__device__ __forceinline__ uint32_t smem_u32(const void* p) {
    uint32_t a;
    asm("{ .reg .u64 t; cvta.to.shared.u64 t, %1; cvt.u32.u64 %0, t; }" : "=r"(a) : "l"(p));
    return a;
}

#define MBAR_INIT(addr, cnt) \
    asm volatile("mbarrier.init.shared.b64 [%0], %1;" :: "r"(addr), "r"(cnt) : "memory")
#define MBAR_EXPECT_TX(addr, bytes) \
    asm volatile("mbarrier.arrive.expect_tx.shared.b64 _, [%0], %1;" :: "r"(addr), "r"(bytes) : "memory")
#define MBAR_ARRIVE(addr) \
    asm volatile("mbarrier.arrive.shared.b64 _, [%0];" :: "r"(addr) : "memory")

#define MBAR_WAIT(addr, ph) do {                                            \
    uint32_t _m = (addr), _p = (ph), _d;                                    \
    asm volatile("{\n\t.reg .pred p;\n\t"                                   \
        "mbarrier.try_wait.parity.acquire.cta.shared::cta.b64 p, [%1], %2;\n\t" \
        "selp.b32 %0, 1, 0, p;\n\t}"                                        \
        : "=r"(_d) : "r"(_m), "r"(_p) : "memory");                          \
    if (!_d) {                                                              \
        asm volatile("{\n\t.reg .pred P1;\n\t"                              \
            "WL_%=:\n\t"                                                    \
            "mbarrier.try_wait.parity.acquire.cta.shared::cta.b64 P1, [%0], %1, 0x989680;\n\t" \
            "@P1 bra.uni WD_%=;\n\t"                                        \
            "bra.uni WL_%=;\n\t"                                            \
            "WD_%=:\n\t}" :: "r"(_m), "r"(_p) : "memory");                  \
    }                                                                       \
} while (0)

__device__ __forceinline__ void bulk_g2s(uint32_t dst, const void* src, uint32_t bytes, uint32_t mbar) {
    asm volatile(
        "cp.async.bulk.shared::cluster.global.mbarrier::complete_tx::bytes [%0], [%1], %2, [%3];"
        :: "r"(dst), "l"(src), "r"(bytes), "r"(mbar) : "memory");
}

__device__ __forceinline__ void ldsm_x4(uint32_t* r, uint32_t addr) {
    asm volatile("ldmatrix.sync.aligned.m8n8.x4.shared.b16 {%0,%1,%2,%3}, [%4];"
                 : "=r"(r[0]), "=r"(r[1]), "=r"(r[2]), "=r"(r[3]) : "r"(addr));
}

__device__ __forceinline__ void mma_bf16(float* c, const uint32_t* a, const uint32_t* b) {
    asm volatile(
        "mma.sync.aligned.m16n8k16.row.col.f32.bf16.bf16.f32 "
        "{%0,%1,%2,%3}, {%4,%5,%6,%7}, {%8,%9}, {%0,%1,%2,%3};"
        : "+f"(c[0]), "+f"(c[1]), "+f"(c[2]), "+f"(c[3])
        : "r"(a[0]), "r"(a[1]), "r"(a[2]), "r"(a[3]), "r"(b[0]), "r"(b[1]));
}

// ---------------------------------------------------------------------------
// Dedup'd packed image: per 128-row block, 64 stored K-blocks = [h: kcol 0..2047 | l: 2048..4095].
// GEMM semantics come from producer stage remaps:
//   left  [h|h|l]: eksL = ks < 32 ? ks : ks - 32
//   right [h;l;h]: eksR = ks < 64 ? ks : ks - 64
// 96 stages: hh+hl+lh ; 64: Ah@B (left) / full (right) ; 32: h@h.
// ---------------------------------------------------------------------------
__device__ __forceinline__ void split8(const float* v, uint4& H, uint4& L) {
    uint32_t h[4], l[4];
#pragma unroll
    for (int i = 0; i < 4; ++i) {
        __nv_bfloat162 h2 = __floats2bfloat162_rn(v[2*i], v[2*i+1]);
        float r0 = v[2*i]   - __bfloat162float(__low2bfloat16(h2));
        float r1 = v[2*i+1] - __bfloat162float(__high2bfloat16(h2));
        __nv_bfloat162 l2 = __floats2bfloat162_rn(r0, r1);
        h[i] = reinterpret_cast<uint32_t&>(h2);
        l[i] = reinterpret_cast<uint32_t&>(l2);
    }
    H = make_uint4(h[0], h[1], h[2], h[3]);
    L = make_uint4(l[0], l[1], l[2], l[3]);
}

__device__ __forceinline__ size_t pk_addr(int row, int kcol) {
    const int rb = row >> 7, rl = row & 127;
    const int ks = kcol >> 6, cl = kcol & 63;
    uint32_t off = (uint32_t)rl * 128 + ((cl >> 3) << 4);
    off ^= (off >> 3) & 0x70;
    return ((size_t)(rb * NSTG_STORED + ks) << 14) + off + ((cl & 7) << 1);
}

// 8 consecutive k-cols (col8 % 8 == 0) = one aligned 16B chunk per segment.
__device__ __forceinline__ void pk_chunk(unsigned char* __restrict__ base, int row, int col8,
                                         const uint4& H, const uint4& L, bool storeL) {
    *(uint4*)(base + pk_addr(row, col8)) = H;
    if (storeL) *(uint4*)(base + pk_addr(row, 2048 + col8)) = L;
}

// read back fp32 x8 from image (h + l), used by MODE 4 epilogue
__device__ __forceinline__ void pk_read8(const unsigned char* __restrict__ base,
                                         int row, int col8, float* x) {
    uint4 H = *(const uint4*)(base + pk_addr(row, col8));
    uint4 L = *(const uint4*)(base + pk_addr(row, 2048 + col8));
    const uint32_t* hp = &H.x;
    const uint32_t* lp = &L.x;
#pragma unroll
    for (int i = 0; i < 4; ++i) {
        __nv_bfloat162 h2 = *reinterpret_cast<const __nv_bfloat162*>(&hp[i]);
        __nv_bfloat162 l2 = *reinterpret_cast<const __nv_bfloat162*>(&lp[i]);
        x[2*i]   = __bfloat162float(__low2bfloat16(h2))  + __bfloat162float(__low2bfloat16(l2));
        x[2*i+1] = __bfloat162float(__high2bfloat16(h2)) + __bfloat162float(__high2bfloat16(l2));
    }
}

// scalar-pair store (skew_pack only)
__device__ __forceinline__ void pk_store_pair(unsigned char* __restrict__ base,
                                              int row, int col, float v0, float v1)
{
    __nv_bfloat162 h2 = __floats2bfloat162_rn(v0, v1);
    float r0 = v0 - __bfloat162float(__low2bfloat16(h2));
    float r1 = v1 - __bfloat162float(__high2bfloat16(h2));
    __nv_bfloat162 l2 = __floats2bfloat162_rn(r0, r1);
    *(uint32_t*)(base + pk_addr(row, col))        = reinterpret_cast<uint32_t&>(h2);
    *(uint32_t*)(base + pk_addr(row, 2048 + col)) = reinterpret_cast<uint32_t&>(l2);
}

// ---------------------------------------------------------------------------
// Half-GEMM over upper-triangle tiles (136 CTAs, single wave).
// acc = Ap @ Bp^T over nstages (producer remaps eksL/eksR). Epilogue:
//  MODE 1 (Y  = X@X,  sym):  D = Y;  PL_Y, PR_Y (h-only) + mirror.
//  MODE 2 (Y2 = Y@Y,  sym):  D = Y2; PR_Y2 (h-only) + mirror.
//  MODE 3 (Y3 = Y@Y2, sym):  D = P = I + e1/2 + e2/24 + acc/720;
//                            PR of Q' = e1/6 + e2/120 + acc/5040 (h+l) + mirror.
//  MODE 4 (out = P + X + X@Q'): D = e1 + Xpk ± acc  (PL param = X image).
// ---------------------------------------------------------------------------
template <int MODE>
__global__ void __launch_bounds__(288, 1)
gemm_half(const unsigned char* __restrict__ Ap, const unsigned char* __restrict__ Bp,
          const float* __restrict__ e1, const float* __restrict__ e2,
          float* __restrict__ D,
          const unsigned char* __restrict__ XI,     // MODE 4: packed X image
          unsigned char* __restrict__ PL, unsigned char* __restrict__ PR,
          int nstages)
{
    extern __shared__ __align__(1024) unsigned char smem[];
    const uint32_t sb = smem_u32(smem);
    const int tid = threadIdx.x;
    const int wid = tid >> 5;
    const int lid = tid & 31;
    const int g = lid >> 2, t = lid & 3;

    // decode upper-triangle tile (mt <= nt)
    int bb = blockIdx.x, mt = 0;
    while (bb >= NTILE - mt) { bb -= NTILE - mt; ++mt; }
    const int nt = mt + bb;

    const int mb = (wid >> 1) * 32;
    const int nb = (wid & 1) * 64;

    if (tid == 0) {
        for (int s = 0; s < STAGES; s++) {
            MBAR_INIT(sb + OFF_FULL  + s * 8, 1);
            MBAR_INIT(sb + OFF_EMPTY + s * 8, 8);
        }
    }
    __syncthreads();

    float acc[2][8][4];
#pragma unroll
    for (int mi = 0; mi < 2; mi++)
#pragma unroll
        for (int j = 0; j < 8; j++)
#pragma unroll
            for (int q = 0; q < 4; q++) acc[mi][j][q] = 0.0f;

    if (wid == 8) {
        // ---- producer with dedup stage remap ----
        if (lid == 0) {
            const unsigned char* srcA = Ap + (size_t)mt * NSTG_STORED * A_STG_BYTES;
            const unsigned char* srcB = Bp + (size_t)nt * NSTG_STORED * B_STG_BYTES;
            int st = 0, ph = 1;
            for (int ks = 0; ks < nstages; ++ks) {
                const int eksL = (ks < 32) ? ks : ks - 32;   // [h|h|l]
                const int eksR = (ks < 64) ? ks : ks - 64;   // [h;l;h]
                MBAR_WAIT(sb + OFF_EMPTY + st * 8, ph);
                MBAR_EXPECT_TX(sb + OFF_FULL + st * 8, A_STG_BYTES + B_STG_BYTES);
                bulk_g2s(sb + OFF_A + st * A_STG_BYTES, srcA + (size_t)eksL * A_STG_BYTES,
                         A_STG_BYTES, sb + OFF_FULL + st * 8);
                bulk_g2s(sb + OFF_B + st * B_STG_BYTES, srcB + (size_t)eksR * B_STG_BYTES,
                         B_STG_BYTES, sb + OFF_FULL + st * 8);
                if (++st == STAGES) { st = 0; ph ^= 1; }
            }
        }
    } else {
        // ---- consumers: warp tile 32(m) x 64(n) ----
        const int rA   = mb + (lid & 15);
        const int chA  = (lid >> 4);
        const uint32_t xorA = (rA & 7) << 4;
        const int rB   = nb + (lid & 7) + ((lid >> 4) << 3);
        const int chB  = (lid >> 3) & 1;
        const uint32_t xorB = (rB & 7) << 4;

        int st = 0, ph = 0;
#pragma unroll 1
        for (int ks = 0; ks < nstages; ++ks) {
            MBAR_WAIT(sb + OFF_FULL + st * 8, ph);
            const uint32_t baseA = sb + OFF_A + st * A_STG_BYTES + (uint32_t)rA * 128;
            const uint32_t baseB = sb + OFF_B + st * B_STG_BYTES + (uint32_t)rB * 128;

#pragma unroll
            for (int kk = 0; kk < 4; ++kk) {
                uint32_t a[2][4];
                const uint32_t kcA = (uint32_t)(kk * 2 + chA) * 16 ^ xorA;
                ldsm_x4(a[0], baseA + kcA);
                ldsm_x4(a[1], baseA + 2048 + kcA);

                uint32_t b[4][4];
                const uint32_t kcB = (uint32_t)(kk * 2 + chB) * 16 ^ xorB;
#pragma unroll
                for (int jj = 0; jj < 4; ++jj)
                    ldsm_x4(b[jj], baseB + (uint32_t)jj * 2048 + kcB);

#pragma unroll
                for (int mi = 0; mi < 2; ++mi)
#pragma unroll
                    for (int j = 0; j < 8; ++j)
                        mma_bf16(acc[mi][j], a[mi], &b[j >> 1][(j & 1) * 2]);
            }

            if (lid == 0) MBAR_ARRIVE(sb + OFF_EMPTY + st * 8);
            if (++st == STAGES) { st = 0; ph ^= 1; }
        }
    }

    // ---- stage acc tile to smem (fp32, stride 132) ----
    __syncthreads();
    float* stg = (float*)(smem + OFF_A);
    if (wid < 8) {
#pragma unroll
        for (int mi = 0; mi < 2; ++mi)
#pragma unroll
            for (int half = 0; half < 2; ++half) {
                const int rl = mb + mi * 16 + half * 8 + g;
#pragma unroll
                for (int j = 0; j < 8; ++j) {
                    const int cl = nb + j * 8 + t * 2;
                    stg[rl * 132 + cl]     = acc[mi][j][half * 2 + 0];
                    stg[rl * 132 + cl + 1] = acc[mi][j][half * 2 + 1];
                }
            }
    }
    __syncthreads();

    // ---- chunked epilogue: 8-element row chunks, all 288 threads ----
    const int rowBase = mt * TILE_M, colBase = nt * TILE_N;
    const bool offd = (mt != nt);

#pragma unroll 1
    for (int task = tid; task < 2048; task += 288) {
        const int rl  = task >> 4;
        const int ch8 = (task & 15) << 3;
        float v[8];
        *(float4*)&v[0] = *(const float4*)&stg[rl * 132 + ch8];
        *(float4*)&v[4] = *(const float4*)&stg[rl * 132 + ch8 + 4];
        const int gr  = rowBase + rl;
        const int gc8 = colBase + ch8;
        const size_t e = (size_t)gr * MATN + gc8;

        if (MODE == 1 || MODE == 2) {
            *(float4*)&D[e]     = *(float4*)&v[0];
            *(float4*)&D[e + 4] = *(float4*)&v[4];
            uint4 H, L; split8(v, H, L);
            if (MODE == 1) pk_chunk(PL, gr, gc8, H, L, false);
            pk_chunk(PR, gr, gc8, H, L, false);
        }
        if (MODE == 3) {
            float y[8], z[8], q[8], p[8];
            *(float4*)&y[0] = *(const float4*)&e1[e]; *(float4*)&y[4] = *(const float4*)&e1[e + 4];
            *(float4*)&z[0] = *(const float4*)&e2[e]; *(float4*)&z[4] = *(const float4*)&e2[e + 4];
#pragma unroll
            for (int i = 0; i < 8; ++i) {
                q[i] = y[i] * (1.0f/6.0f) + z[i] * (1.0f/120.0f) + v[i] * (1.0f/5040.0f);
                p[i] = y[i] * 0.5f        + z[i] * (1.0f/24.0f)  + v[i] * (1.0f/720.0f);
            }
            const int d = gr - gc8;
            if (d >= 0 && d < 8) p[d] += 1.0f;    // P gets +I; Q' does not
            *(float4*)&D[e]     = *(float4*)&p[0];
            *(float4*)&D[e + 4] = *(float4*)&p[4];
            uint4 H, L; split8(q, H, L);
            pk_chunk(PR, gr, gc8, H, L, true);
        }
        if (MODE == 4) {
            float p[8], x[8];
            *(float4*)&p[0] = *(const float4*)&e1[e]; *(float4*)&p[4] = *(const float4*)&e1[e + 4];
            pk_read8(XI, gr, gc8, x);
#pragma unroll
            for (int i = 0; i < 8; ++i) p[i] += x[i] + v[i];
            *(float4*)&D[e]     = *(float4*)&p[0];
            *(float4*)&D[e + 4] = *(float4*)&p[4];
        }
    }

    if (offd) {
        // mirror: row gr = colBase + cc, cols gc8 = rowBase + chb8..
#pragma unroll 1
        for (int task = tid; task < 2048; task += 288) {
            const int cc   = task >> 4;
            const int chb8 = (task & 15) << 3;
            float v[8];
#pragma unroll
            for (int k = 0; k < 8; ++k) v[k] = stg[(chb8 + k) * 132 + cc];
            const int gr  = colBase + cc;
            const int gc8 = rowBase + chb8;
            const size_t e = (size_t)gr * MATN + gc8;

            if (MODE == 1 || MODE == 2) {
                *(float4*)&D[e]     = *(float4*)&v[0];
                *(float4*)&D[e + 4] = *(float4*)&v[4];
                uint4 H, L; split8(v, H, L);
                if (MODE == 1) pk_chunk(PL, gr, gc8, H, L, false);
                pk_chunk(PR, gr, gc8, H, L, false);
            }
            if (MODE == 3) {
                float y[8], z[8], q[8], p[8];
                *(float4*)&y[0] = *(const float4*)&e1[e]; *(float4*)&y[4] = *(const float4*)&e1[e + 4];
                *(float4*)&z[0] = *(const float4*)&e2[e]; *(float4*)&z[4] = *(const float4*)&e2[e + 4];
#pragma unroll
                for (int i = 0; i < 8; ++i) {
                    q[i] = y[i] * (1.0f/6.0f) + z[i] * (1.0f/120.0f) + v[i] * (1.0f/5040.0f);
                    p[i] = y[i] * 0.5f        + z[i] * (1.0f/24.0f)  + v[i] * (1.0f/720.0f);
                }
                *(float4*)&D[e]     = *(float4*)&p[0];
                *(float4*)&D[e + 4] = *(float4*)&p[4];
                uint4 H, L; split8(q, H, L);
                pk_chunk(PR, gr, gc8, H, L, true);
            }
            if (MODE == 4) {
                float p[8], x[8];
                *(float4*)&p[0] = *(const float4*)&e1[e]; *(float4*)&p[4] = *(const float4*)&e1[e + 4];
                pk_read8(XI, gr, gc8, x);   // X at mirror position (sign included)
#pragma unroll
                for (int i = 0; i < 8; ++i) p[i] += x[i] - v[i];   // acc antisym
                *(float4*)&D[e]     = *(float4*)&p[0];
                *(float4*)&D[e + 4] = *(float4*)&p[4];
            }
        }
    }
}

// ---------------------------------------------------------------------------
// skew_pack: X = A - A^T packed only: PL_X (rows of X), PR_X (rows of -X).
// ---------------------------------------------------------------------------
__global__ void skew_pack(const float* __restrict__ A,
                          unsigned char* __restrict__ PL, unsigned char* __restrict__ PR)
{
    __shared__ float tT[32][33];
    const int rblk = blockIdx.y * 32, cblk = blockIdx.x * 32;
    const int tfl = threadIdx.y * 16 + threadIdx.x;
#pragma unroll
    for (int e = tfl; e < 1024; e += 512) {
        const int u = e >> 5, v = e & 31;
        tT[u][v] = A[(size_t)(cblk + u) * MATN + rblk + v];
    }
    __syncthreads();
    const int r = rblk + threadIdx.y;
    const int c0 = cblk + threadIdx.x * 2;
    float2 av = *(const float2*)(A + (size_t)r * MATN + c0);
    const float x0 = av.x - tT[threadIdx.x * 2][threadIdx.y];
    const float x1 = av.y - tT[threadIdx.x * 2 + 1][threadIdx.y];
    pk_store_pair(PL, r, c0, x0, x1);
    pk_store_pair(PR, r, c0, -x0, -x1);
}

// ---------------------------------------------------------------------------
// expm(A - A^T) via even/odd split, degree 7 in X (cubic in Y = X^2):
//   Y = X^2 (96 stg); Y2 = Y^2 (32); Y3 = Y*Y2 (32, folds P, packs Q' = Q - I)
//   out = P + X + X@Q' (64 stg: Xh @ full Q'; X restored exactly from image)
// ---------------------------------------------------------------------------
extern "C" void kernel_launch(void* const* d_in, const int* in_sizes, int n_in,
                              void* d_out, int out_size)
{
    const float* A = (const float*)d_in[0];
    float* out = (float*)d_out;

    float* fbase = nullptr;
    cudaGetSymbolAddress((void**)&fbase, g_f);
    float* Y  = fbase + 0 * (size_t)NN;
    float* Y2 = fbase + 1 * (size_t)NN;
    float* P  = fbase + 2 * (size_t)NN;

    unsigned char* pbase = nullptr;
    cudaGetSymbolAddress((void**)&pbase, g_pk);
    unsigned char* PL_X  = pbase + 0 * PK_BYTES;
    unsigned char* PR_X  = pbase + 1 * PK_BYTES;
    unsigned char* PL_Y  = pbase + 2 * PK_BYTES;
    unsigned char* PR_Y  = pbase + 3 * PK_BYTES;
    unsigned char* PR_Y2 = pbase + 4 * PK_BYTES;
    unsigned char* PR_Q  = pbase + 5 * PK_BYTES;

    cudaFuncSetAttribute(gemm_half<1>, cudaFuncAttributeMaxDynamicSharedMemorySize, SMEM_BYTES);
    cudaFuncSetAttribute(gemm_half<2>, cudaFuncAttributeMaxDynamicSharedMemorySize, SMEM_BYTES);
    cudaFuncSetAttribute(gemm_half<3>, cudaFuncAttributeMaxDynamicSharedMemorySize, SMEM_BYTES);
    cudaFuncSetAttribute(gemm_half<4>, cudaFuncAttributeMaxDynamicSharedMemorySize, SMEM_BYTES);

    const dim3 sGrid(MATN / 32, MATN / 32);
    const dim3 sBlk(16, 32);

    // packs of X (h+l)
    skew_pack<<<sGrid, sBlk>>>(A, PL_X, PR_X);
    // Y = X @ X                (full split: 96 stages) -> Y fp32, PL_Y/PR_Y h-only
    gemm_half<1><<<NBLK, 288, SMEM_BYTES>>>(PL_X, PR_X, nullptr, nullptr,
                                            Y, nullptr, PL_Y, PR_Y, 96);
    // Y2 = Y @ Y               (Yh @ Yh: 32 stages) -> Y2 fp32, PR_Y2 h-only
    gemm_half<2><<<NBLK, 288, SMEM_BYTES>>>(PL_Y, PR_Y, nullptr, nullptr,
                                            Y2, nullptr, nullptr, PR_Y2, 32);
    // Y3 = Y @ Y2 (32 stg); epilogue: P fp32 full, Q' packed (h+l)
    gemm_half<3><<<NBLK, 288, SMEM_BYTES>>>(PL_Y, PR_Y2, Y, Y2,
                                            P, nullptr, nullptr, PR_Q, 32);
    // out = P + X + X @ Q'     (Xh @ Q' full: 64 stages)
    gemm_half<4><<<NBLK, 288, SMEM_BYTES>>>(PL_X, PR_Q, P, nullptr,
                                            out, PL_X, nullptr, nullptr, 64);
}

// round 17
// speedup vs baseline: 19.4145x; 1.2943x over previous
#include <cuda_runtime.h>
#include <cuda_bf16.h>
#include <cstdint>

#define MATN 2048
#define NN (MATN * MATN)
#define KC   64
#define STAGES 4
#define TILE_M 128
#define TILE_N 128
#define NTILE (MATN / TILE_M)     // 16
#define NBLK  (NTILE * (NTILE + 1) / 2)   // 136 upper-triangle tiles
#define NSTG_STORED 64            // stored K-blocks per image row-block: [h:32 | l:32]

#define A_STG_BYTES (TILE_M * 128)
#define B_STG_BYTES (TILE_N * 128)

#define OFF_FULL   0
#define OFF_EMPTY  32
#define OFF_A      1024
#define OFF_B      (OFF_A + STAGES * A_STG_BYTES)
#define SMEM_BYTES (OFF_B + STAGES * B_STG_BYTES)      // 132096
// epilogue staging reuses [OFF_A, OFF_A + 128*132*4) < SMEM_BYTES

#define PK_BYTES ((size_t)MATN * 4096 * 2)   // 16 MB per dedup'd image

// ---------------------------------------------------------------------------
// Scratch: 5 packed bf16 images only (no fp32 intermediates at all):
//   [0] IX  = X rows (h+l)      [1] IY  = Y (h+l, sym: left==right image)
//   [2] IY2 = Y2 (h+l)          [3] IQ  = Q' (h only)       [4] IP = P (h+l)
// ---------------------------------------------------------------------------
__device__ __align__(128) unsigned char g_pk[5][PK_BYTES];

// ---------------------------------------------------------------------------
// PTX helpers (compute_103-safe)
// ---------------------------------------------------------------------------
__device__ __forceinline__ uint32_t smem_u32(const void* p) {
    uint32_t a;
    asm("{ .reg .u64 t; cvta.to.shared.u64 t, %1; cvt.u32.u64 %0, t; }" : "=r"(a) : "l"(p));
    return a;
}

#define MBAR_INIT(addr, cnt) \
    asm volatile("mbarrier.init.shared.b64 [%0], %1;" :: "r"(addr), "r"(cnt) : "memory")
#define MBAR_EXPECT_TX(addr, bytes) \
    asm volatile("mbarrier.arrive.expect_tx.shared.b64 _, [%0], %1;" :: "r"(addr), "r"(bytes) : "memory")
#define MBAR_ARRIVE(addr) \
    asm volatile("mbarrier.arrive.shared.b64 _, [%0];" :: "r"(addr) : "memory")

#define MBAR_WAIT(addr, ph) do {                                            \
    uint32_t _m = (addr), _p = (ph), _d;                                    \
    asm volatile("{\n\t.reg .pred p;\n\t"                                   \
        "mbarrier.try_wait.parity.acquire.cta.shared::cta.b64 p, [%1], %2;\n\t" \
        "selp.b32 %0, 1, 0, p;\n\t}"                                        \
        : "=r"(_d) : "r"(_m), "r"(_p) : "memory");                          \
    if (!_d) {                                                              \
        asm volatile("{\n\t.reg .pred P1;\n\t"                              \
            "WL_%=:\n\t"                                                    \
            "mbarrier.try_wait.parity.acquire.cta.shared::cta.b64 P1, [%0], %1, 0x989680;\n\t" \
            "@P1 bra.uni WD_%=;\n\t"                                        \
            "bra.uni WL_%=;\n\t"                                            \
            "WD_%=:\n\t}" :: "r"(_m), "r"(_p) : "memory");                  \
    }                                                                       \
} while (0)

__device__ __forceinline__ void bulk_g2s(uint32_t dst, const void* src, uint32_t bytes, uint32_t mbar) {
    asm volatile(
        "cp.async.bulk.shared::cluster.global.mbarrier::complete_tx::bytes [%0], [%1], %2, [%3];"
        :: "r"(dst), "l"(src), "r"(bytes), "r"(mbar) : "memory");
}

__device__ __forceinline__ void ldsm_x4(uint32_t* r, uint32_t addr) {
    asm volatile("ldmatrix.sync.aligned.m8n8.x4.shared.b16 {%0,%1,%2,%3}, [%4];"
                 : "=r"(r[0]), "=r"(r[1]), "=r"(r[2]), "=r"(r[3]) : "r"(addr));
}

__device__ __forceinline__ void mma_bf16(float* c, const uint32_t* a, const uint32_t* b) {
    asm volatile(
        "mma.sync.aligned.m16n8k16.row.col.f32.bf16.bf16.f32 "
        "{%0,%1,%2,%3}, {%4,%5,%6,%7}, {%8,%9}, {%0,%1,%2,%3};"
        : "+f"(c[0]), "+f"(c[1]), "+f"(c[2]), "+f"(c[3])
        : "r"(a[0]), "r"(a[1]), "r"(a[2]), "r"(a[3]), "r"(b[0]), "r"(b[1]));
}

// ---------------------------------------------------------------------------
// Dedup'd image: per 128-row block, 64 K-blocks = [h: kcol 0..2047 | l: 2048..4095].
// GEMM semantics from producer stage remaps (eksL: h,h,l ; eksR: h,l,h):
//   96 stg: AhBh+AhBl+AlBh ; 64: Ah@(Bh+Bl) ; 32: Ah@Bh.
// The GEMM computes acc[m][n] = sum_k Aimg[m][k]*Bimg[n][k] = Aimg @ Bimg^T.
// For symmetric operands the row image serves both sides; feeding IX on both
// sides of G1 gives Xh @ X^T = -Y (negated in the epilogue).
// ---------------------------------------------------------------------------
__device__ __forceinline__ void split8(const float* v, uint4& H, uint4& L) {
    uint32_t h[4], l[4];
#pragma unroll
    for (int i = 0; i < 4; ++i) {
        __nv_bfloat162 h2 = __floats2bfloat162_rn(v[2*i], v[2*i+1]);
        float r0 = v[2*i]   - __bfloat162float(__low2bfloat16(h2));
        float r1 = v[2*i+1] - __bfloat162float(__high2bfloat16(h2));
        __nv_bfloat162 l2 = __floats2bfloat162_rn(r0, r1);
        h[i] = reinterpret_cast<uint32_t&>(h2);
        l[i] = reinterpret_cast<uint32_t&>(l2);
    }
    H = make_uint4(h[0], h[1], h[2], h[3]);
    L = make_uint4(l[0], l[1], l[2], l[3]);
}

__device__ __forceinline__ size_t pk_addr(int row, int kcol) {
    const int rb = row >> 7, rl = row & 127;
    const int ks = kcol >> 6, cl = kcol & 63;
    uint32_t off = (uint32_t)rl * 128 + ((cl >> 3) << 4);
    off ^= (off >> 3) & 0x70;
    return ((size_t)(rb * NSTG_STORED + ks) << 14) + off + ((cl & 7) << 1);
}

__device__ __forceinline__ void pk_chunk(unsigned char* __restrict__ base, int row, int col8,
                                         const uint4& H, const uint4& L, bool storeL) {
    *(uint4*)(base + pk_addr(row, col8)) = H;
    if (storeL) *(uint4*)(base + pk_addr(row, 2048 + col8)) = L;
}

// fp32 x8 read-back from image (h + l)
__device__ __forceinline__ void pk_read8(const unsigned char* __restrict__ base,
                                         int row, int col8, float* x) {
    uint4 H = *(const uint4*)(base + pk_addr(row, col8));
    uint4 L = *(const uint4*)(base + pk_addr(row, 2048 + col8));
    const uint32_t* hp = &H.x;
    const uint32_t* lp = &L.x;
#pragma unroll
    for (int i = 0; i < 4; ++i) {
        __nv_bfloat162 h2 = *reinterpret_cast<const __nv_bfloat162*>(&hp[i]);
        __nv_bfloat162 l2 = *reinterpret_cast<const __nv_bfloat162*>(&lp[i]);
        x[2*i]   = __bfloat162float(__low2bfloat16(h2))  + __bfloat162float(__low2bfloat16(l2));
        x[2*i+1] = __bfloat162float(__high2bfloat16(h2)) + __bfloat162float(__high2bfloat16(l2));
    }
}

// scalar-pair store (skew_pack only)
__device__ __forceinline__ void pk_store_pair(unsigned char* __restrict__ base,
                                              int row, int col, float v0, float v1)
{
    __nv_bfloat162 h2 = __floats2bfloat162_rn(v0, v1);
    float r0 = v0 - __bfloat162float(__low2bfloat16(h2));
    float r1 = v1 - __bfloat162float(__high2bfloat16(h2));
    __nv_bfloat162 l2 = __floats2bfloat162_rn(r0, r1);
    *(uint32_t*)(base + pk_addr(row, col))        = reinterpret_cast<uint32_t&>(h2);
    *(uint32_t*)(base + pk_addr(row, 2048 + col)) = reinterpret_cast<uint32_t&>(l2);
}

// ---------------------------------------------------------------------------
// Half-GEMM over upper-triangle tiles (136 CTAs, single wave).
//  MODE 1 (G1): acc = Xh@X^T = -Y  ->  IY = -acc (h+l) + mirror.
//  MODE 2 (G2): acc = Yh@Yh = Y2   ->  IY2 (h+l) + mirror.
//  MODE 3 (G3): acc = Yh@Y2h = Y3; read IY, IY2:
//               IQ = Y/6 + Y2/120 + Y3/5040 (h only); IP = I + Y/2 + Y2/24 + Y3/720 (h+l).
//  MODE 4 (G4): acc = Xh@Q'h; out = P + X + acc (mirror: P + X - acc).
// ---------------------------------------------------------------------------
template <int MODE>
__global__ void __launch_bounds__(288, 1)
gemm_half(const unsigned char* __restrict__ Ap, const unsigned char* __restrict__ Bp,
          const unsigned char* __restrict__ in1, const unsigned char* __restrict__ in2,
          const unsigned char* __restrict__ inX,
          float* __restrict__ D,
          unsigned char* __restrict__ o1, unsigned char* __restrict__ o2,
          int nstages)
{
    extern __shared__ __align__(1024) unsigned char smem[];
    const uint32_t sb = smem_u32(smem);
    const int tid = threadIdx.x;
    const int wid = tid >> 5;
    const int lid = tid & 31;
    const int g = lid >> 2, t = lid & 3;

    // decode upper-triangle tile (mt <= nt)
    int bb = blockIdx.x, mt = 0;
    while (bb >= NTILE - mt) { bb -= NTILE - mt; ++mt; }
    const int nt = mt + bb;

    const int mb = (wid >> 1) * 32;
    const int nb = (wid & 1) * 64;

    if (tid == 0) {
        for (int s = 0; s < STAGES; s++) {
            MBAR_INIT(sb + OFF_FULL  + s * 8, 1);
            MBAR_INIT(sb + OFF_EMPTY + s * 8, 8);
        }
    }
    __syncthreads();

    float acc[2][8][4];
#pragma unroll
    for (int mi = 0; mi < 2; mi++)
#pragma unroll
        for (int j = 0; j < 8; j++)
#pragma unroll
            for (int q = 0; q < 4; q++) acc[mi][j][q] = 0.0f;

    if (wid == 8) {
        // ---- producer with dedup stage remap ----
        if (lid == 0) {
            const unsigned char* srcA = Ap + (size_t)mt * NSTG_STORED * A_STG_BYTES;
            const unsigned char* srcB = Bp + (size_t)nt * NSTG_STORED * B_STG_BYTES;
            int st = 0, ph = 1;
            for (int ks = 0; ks < nstages; ++ks) {
                const int eksL = (ks < 32) ? ks : ks - 32;   // [h|h|l]
                const int eksR = (ks < 64) ? ks : ks - 64;   // [h;l;h]
                MBAR_WAIT(sb + OFF_EMPTY + st * 8, ph);
                MBAR_EXPECT_TX(sb + OFF_FULL + st * 8, A_STG_BYTES + B_STG_BYTES);
                bulk_g2s(sb + OFF_A + st * A_STG_BYTES, srcA + (size_t)eksL * A_STG_BYTES,
                         A_STG_BYTES, sb + OFF_FULL + st * 8);
                bulk_g2s(sb + OFF_B + st * B_STG_BYTES, srcB + (size_t)eksR * B_STG_BYTES,
                         B_STG_BYTES, sb + OFF_FULL + st * 8);
                if (++st == STAGES) { st = 0; ph ^= 1; }
            }
        }
    } else {
        // ---- consumers: warp tile 32(m) x 64(n) ----
        const int rA   = mb + (lid & 15);
        const int chA  = (lid >> 4);
        const uint32_t xorA = (rA & 7) << 4;
        const int rB   = nb + (lid & 7) + ((lid >> 4) << 3);
        const int chB  = (lid >> 3) & 1;
        const uint32_t xorB = (rB & 7) << 4;

        int st = 0, ph = 0;
#pragma unroll 1
        for (int ks = 0; ks < nstages; ++ks) {
            MBAR_WAIT(sb + OFF_FULL + st * 8, ph);
            const uint32_t baseA = sb + OFF_A + st * A_STG_BYTES + (uint32_t)rA * 128;
            const uint32_t baseB = sb + OFF_B + st * B_STG_BYTES + (uint32_t)rB * 128;

#pragma unroll
            for (int kk = 0; kk < 4; ++kk) {
                uint32_t a[2][4];
                const uint32_t kcA = (uint32_t)(kk * 2 + chA) * 16 ^ xorA;
                ldsm_x4(a[0], baseA + kcA);
                ldsm_x4(a[1], baseA + 2048 + kcA);

                uint32_t b[4][4];
                const uint32_t kcB = (uint32_t)(kk * 2 + chB) * 16 ^ xorB;
#pragma unroll
                for (int jj = 0; jj < 4; ++jj)
                    ldsm_x4(b[jj], baseB + (uint32_t)jj * 2048 + kcB);

#pragma unroll
                for (int mi = 0; mi < 2; ++mi)
#pragma unroll
                    for (int j = 0; j < 8; ++j)
                        mma_bf16(acc[mi][j], a[mi], &b[j >> 1][(j & 1) * 2]);
            }

            if (lid == 0) MBAR_ARRIVE(sb + OFF_EMPTY + st * 8);
            if (++st == STAGES) { st = 0; ph ^= 1; }
        }
    }

    // ---- stage acc tile to smem (fp32, stride 132) ----
    __syncthreads();
    float* stg = (float*)(smem + OFF_A);
    if (wid < 8) {
#pragma unroll
        for (int mi = 0; mi < 2; ++mi)
#pragma unroll
            for (int half = 0; half < 2; ++half) {
                const int rl = mb + mi * 16 + half * 8 + g;
#pragma unroll
                for (int j = 0; j < 8; ++j) {
                    const int cl = nb + j * 8 + t * 2;
                    stg[rl * 132 + cl]     = acc[mi][j][half * 2 + 0];
                    stg[rl * 132 + cl + 1] = acc[mi][j][half * 2 + 1];
                }
            }
    }
    __syncthreads();

    // ---- chunked epilogue: 8-element row chunks, all 288 threads ----
    const int rowBase = mt * TILE_M, colBase = nt * TILE_N;
    const bool offd = (mt != nt);

#pragma unroll 1
    for (int task = tid; task < 2048; task += 288) {
        const int rl  = task >> 4;
        const int ch8 = (task & 15) << 3;
        float v[8];
        *(float4*)&v[0] = *(const float4*)&stg[rl * 132 + ch8];
        *(float4*)&v[4] = *(const float4*)&stg[rl * 132 + ch8 + 4];
        const int gr  = rowBase + rl;
        const int gc8 = colBase + ch8;

        if (MODE == 1 || MODE == 2) {
            if (MODE == 1) {
#pragma unroll
                for (int i = 0; i < 8; ++i) v[i] = -v[i];   // acc = -Y
            }
            uint4 H, L; split8(v, H, L);
            pk_chunk(o1, gr, gc8, H, L, true);
        }
        if (MODE == 3) {
            float y[8], z[8], q[8], p[8];
            pk_read8(in1, gr, gc8, y);
            pk_read8(in2, gr, gc8, z);
#pragma unroll
            for (int i = 0; i < 8; ++i) {
                q[i] = y[i] * (1.0f/6.0f) + z[i] * (1.0f/120.0f) + v[i] * (1.0f/5040.0f);
                p[i] = y[i] * 0.5f        + z[i] * (1.0f/24.0f)  + v[i] * (1.0f/720.0f);
            }
            const int d = gr - gc8;
            if (d >= 0 && d < 8) p[d] += 1.0f;    // +I on P only (Q' has none)
            uint4 H, L; split8(q, H, L);
            pk_chunk(o1, gr, gc8, H, L, false);   // IQ: h only
            split8(p, H, L);
            pk_chunk(o2, gr, gc8, H, L, true);    // IP: h+l
        }
        if (MODE == 4) {
            float p[8], x[8];
            pk_read8(in2, gr, gc8, p);
            pk_read8(inX, gr, gc8, x);
            const size_t e = (size_t)gr * MATN + gc8;
#pragma unroll
            for (int i = 0; i < 8; ++i) p[i] += x[i] + v[i];
            *(float4*)&D[e]     = *(float4*)&p[0];
            *(float4*)&D[e + 4] = *(float4*)&p[4];
        }
    }

    if (offd) {
        // mirror: row gr = colBase + cc, cols gc8 = rowBase + chb8..
#pragma unroll 1
        for (int task = tid; task < 2048; task += 288) {
            const int cc   = task >> 4;
            const int chb8 = (task & 15) << 3;
            float v[8];
#pragma unroll
            for (int k = 0; k < 8; ++k) v[k] = stg[(chb8 + k) * 132 + cc];
            const int gr  = colBase + cc;
            const int gc8 = rowBase + chb8;

            if (MODE == 1 || MODE == 2) {
                if (MODE == 1) {
#pragma unroll
                    for (int i = 0; i < 8; ++i) v[i] = -v[i];
                }
                uint4 H, L; split8(v, H, L);
                pk_chunk(o1, gr, gc8, H, L, true);
            }
            if (MODE == 3) {
                float y[8], z[8], q[8], p[8];
                pk_read8(in1, gr, gc8, y);
                pk_read8(in2, gr, gc8, z);
#pragma unroll
                for (int i = 0; i < 8; ++i) {
                    q[i] = y[i] * (1.0f/6.0f) + z[i] * (1.0f/120.0f) + v[i] * (1.0f/5040.0f);
                    p[i] = y[i] * 0.5f        + z[i] * (1.0f/24.0f)  + v[i] * (1.0f/720.0f);
                }
                uint4 H, L; split8(q, H, L);
                pk_chunk(o1, gr, gc8, H, L, false);
                split8(p, H, L);
                pk_chunk(o2, gr, gc8, H, L, true);
            }
            if (MODE == 4) {
                float p[8], x[8];
                pk_read8(in2, gr, gc8, p);
                pk_read8(inX, gr, gc8, x);   // X at mirror position (sign baked in image)
                const size_t e = (size_t)gr * MATN + gc8;
#pragma unroll
                for (int i = 0; i < 8; ++i) p[i] += x[i] - v[i];   // acc antisym
                *(float4*)&D[e]     = *(float4*)&p[0];
                *(float4*)&D[e + 4] = *(float4*)&p[4];
            }
        }
    }
}

// ---------------------------------------------------------------------------
// skew_pack: X = A - A^T, packed row image IX (h+l) only.
// ---------------------------------------------------------------------------
__global__ void skew_pack(const float* __restrict__ A, unsigned char* __restrict__ IX)
{
    __shared__ float tT[32][33];
    const int rblk = blockIdx.y * 32, cblk = blockIdx.x * 32;
    const int tfl = threadIdx.y * 16 + threadIdx.x;
#pragma unroll
    for (int e = tfl; e < 1024; e += 512) {
        const int u = e >> 5, v = e & 31;
        tT[u][v] = A[(size_t)(cblk + u) * MATN + rblk + v];
    }
    __syncthreads();
    const int r = rblk + threadIdx.y;
    const int c0 = cblk + threadIdx.x * 2;
    float2 av = *(const float2*)(A + (size_t)r * MATN + c0);
    const float x0 = av.x - tT[threadIdx.x * 2][threadIdx.y];
    const float x1 = av.y - tT[threadIdx.x * 2 + 1][threadIdx.y];
    pk_store_pair(IX, r, c0, x0, x1);
}

// ---------------------------------------------------------------------------
// expm(A - A^T), even/odd split, degree 7 in X (cubic in Y = X^2), all
// intermediates bf16(h+l) images, all GEMMs half (upper-triangle) single-wave:
//   G1 (64 stg): IY  = -(Xh @ X^T) = Xh@X
//   G2 (32 stg): IY2 = Yh @ Yh
//   G3 (32 stg): Y3 = Yh @ Y2h; pack IQ = Y/6+Y2/120+Y3/5040 (h), IP = I+Y/2+Y2/24+Y3/720
//   G4 (32 stg): out = P + X + Xh @ Q'h
// ---------------------------------------------------------------------------
extern "C" void kernel_launch(void* const* d_in, const int* in_sizes, int n_in,
                              void* d_out, int out_size)
{
    const float* A = (const float*)d_in[0];
    float* out = (float*)d_out;

    unsigned char* pbase = nullptr;
    cudaGetSymbolAddress((void**)&pbase, g_pk);
    unsigned char* IX  = pbase + 0 * PK_BYTES;
    unsigned char* IY  = pbase + 1 * PK_BYTES;
    unsigned char* IY2 = pbase + 2 * PK_BYTES;
    unsigned char* IQ  = pbase + 3 * PK_BYTES;
    unsigned char* IP  = pbase + 4 * PK_BYTES;

    cudaFuncSetAttribute(gemm_half<1>, cudaFuncAttributeMaxDynamicSharedMemorySize, SMEM_BYTES);
    cudaFuncSetAttribute(gemm_half<2>, cudaFuncAttributeMaxDynamicSharedMemorySize, SMEM_BYTES);
    cudaFuncSetAttribute(gemm_half<3>, cudaFuncAttributeMaxDynamicSharedMemorySize, SMEM_BYTES);
    cudaFuncSetAttribute(gemm_half<4>, cudaFuncAttributeMaxDynamicSharedMemorySize, SMEM_BYTES);

    const dim3 sGrid(MATN / 32, MATN / 32);
    const dim3 sBlk(16, 32);

    // IX = pack(A - A^T)
    skew_pack<<<sGrid, sBlk>>>(A, IX);
    // G1: IY = Xh @ X (64 stages; right image = IX -> acc = -Y, negated in epilogue)
    gemm_half<1><<<NBLK, 288, SMEM_BYTES>>>(IX, IX, nullptr, nullptr, nullptr,
                                            nullptr, IY, nullptr, 64);
    // G2: IY2 = Yh @ Yh (32 stages)
    gemm_half<2><<<NBLK, 288, SMEM_BYTES>>>(IY, IY, nullptr, nullptr, nullptr,
                                            nullptr, IY2, nullptr, 32);
    // G3: Y3 = Yh @ Y2h (32 stages); epilogue packs IQ (h) and IP (h+l)
    gemm_half<3><<<NBLK, 288, SMEM_BYTES>>>(IY, IY2, IY, IY2, nullptr,
                                            nullptr, IQ, IP, 32);
    // G4: out = P + X + Xh @ Q'h (32 stages)
    gemm_half<4><<<NBLK, 288, SMEM_BYTES>>>(IX, IQ, nullptr, IP, IX,
                                            out, nullptr, nullptr, 32);
}